// round 2
// baseline (speedup 1.0000x reference)
#include <cuda_runtime.h>
#include <cuda_bf16.h>
#include <math.h>

#define NSEQ 2048
#define HID  2048
#define NH   32
#define DK   128
#define PROJ 4096
#define QSCALE 0.08838834764831843f   // 128^-0.5

// ---------------- scratch (device globals; no allocation allowed) ----------------
__device__ float g_Qp[NSEQ * PROJ];
__device__ float g_Kp[NSEQ * PROJ];
__device__ float g_Vp[NSEQ * PROJ];
__device__ float g_Qc[NSEQ * PROJ];
__device__ float g_Kc[NSEQ * PROJ];
__device__ float g_Vc[NSEQ * PROJ];
__device__ float g_F[NSEQ * PROJ];     // f, overwritten in-place with exp(g)
__device__ float g_GATE[NSEQ * PROJ];  // gate pre-activation
__device__ float g_CORE[NSEQ * PROJ];  // scan output, then gated-rms output in place
__device__ float g_FA[NSEQ * DK];
__device__ float g_GA[NSEQ * DK];
__device__ float g_BRAW[NSEQ * NH];

// ---------------- generic C = A[M,K] * B[N,K]^T (both row-major) ----------------
// 128x128 block tile, 16 K-tile, 8x8 per-thread register tile, 256 threads,
// register prefetch of next global tile.
__global__ void __launch_bounds__(256) gemm_nt_kernel(
    const float* __restrict__ A, const float* __restrict__ B, float* __restrict__ C,
    int M, int Nn, int Kd) {
  __shared__ float As[16][132];
  __shared__ float Bs[16][132];
  const int tid  = threadIdx.x;
  const int bm   = blockIdx.y * 128;
  const int bn   = blockIdx.x * 128;
  const int tx   = tid & 15;
  const int ty   = tid >> 4;
  const int row0 = ty * 8;
  const int col0 = tx * 8;
  const int lr   = tid >> 1;        // 0..127
  const int lc   = (tid & 1) * 8;   // 0 or 8

  const float* Aptr = A + (size_t)(bm + lr) * Kd + lc;
  const bool bvalid = (bn + lr) < Nn;
  const float* Bptr = B + (size_t)(bn + lr) * Kd + lc;

  float4 pa0, pa1, pb0, pb1;
  pa0 = *reinterpret_cast<const float4*>(Aptr);
  pa1 = *reinterpret_cast<const float4*>(Aptr + 4);
  if (bvalid) {
    pb0 = *reinterpret_cast<const float4*>(Bptr);
    pb1 = *reinterpret_cast<const float4*>(Bptr + 4);
  } else {
    pb0 = make_float4(0.f, 0.f, 0.f, 0.f);
    pb1 = pb0;
  }

  float acc[8][8];
#pragma unroll
  for (int i = 0; i < 8; i++)
#pragma unroll
    for (int j = 0; j < 8; j++) acc[i][j] = 0.f;

  for (int k0 = 0; k0 < Kd; k0 += 16) {
    // store prefetched tiles (transposed: [k][m])
    As[lc + 0][lr] = pa0.x; As[lc + 1][lr] = pa0.y;
    As[lc + 2][lr] = pa0.z; As[lc + 3][lr] = pa0.w;
    As[lc + 4][lr] = pa1.x; As[lc + 5][lr] = pa1.y;
    As[lc + 6][lr] = pa1.z; As[lc + 7][lr] = pa1.w;
    Bs[lc + 0][lr] = pb0.x; Bs[lc + 1][lr] = pb0.y;
    Bs[lc + 2][lr] = pb0.z; Bs[lc + 3][lr] = pb0.w;
    Bs[lc + 4][lr] = pb1.x; Bs[lc + 5][lr] = pb1.y;
    Bs[lc + 6][lr] = pb1.z; Bs[lc + 7][lr] = pb1.w;
    __syncthreads();

    const int kn = k0 + 16;
    if (kn < Kd) {
      pa0 = *reinterpret_cast<const float4*>(Aptr + kn);
      pa1 = *reinterpret_cast<const float4*>(Aptr + kn + 4);
      if (bvalid) {
        pb0 = *reinterpret_cast<const float4*>(Bptr + kn);
        pb1 = *reinterpret_cast<const float4*>(Bptr + kn + 4);
      }
    }

#pragma unroll
    for (int kk = 0; kk < 16; kk++) {
      float a[8], b[8];
      float4 t0 = *reinterpret_cast<const float4*>(&As[kk][row0]);
      float4 t1 = *reinterpret_cast<const float4*>(&As[kk][row0 + 4]);
      float4 u0 = *reinterpret_cast<const float4*>(&Bs[kk][col0]);
      float4 u1 = *reinterpret_cast<const float4*>(&Bs[kk][col0 + 4]);
      a[0] = t0.x; a[1] = t0.y; a[2] = t0.z; a[3] = t0.w;
      a[4] = t1.x; a[5] = t1.y; a[6] = t1.z; a[7] = t1.w;
      b[0] = u0.x; b[1] = u0.y; b[2] = u0.z; b[3] = u0.w;
      b[4] = u1.x; b[5] = u1.y; b[6] = u1.z; b[7] = u1.w;
#pragma unroll
      for (int i = 0; i < 8; i++)
#pragma unroll
        for (int j = 0; j < 8; j++) acc[i][j] = fmaf(a[i], b[j], acc[i][j]);
    }
    __syncthreads();
  }

#pragma unroll
  for (int i = 0; i < 8; i++) {
    float* Cr = C + (size_t)(bm + row0 + i) * Nn;
#pragma unroll
    for (int j = 0; j < 8; j++) {
      int cc = bn + col0 + j;
      if (cc < Nn) Cr[cc] = acc[i][j];
    }
  }
}

// -------- depthwise causal conv(K=4) + SiLU, optional per-(n,h) L2 norm --------
__global__ void __launch_bounds__(128) conv_silu_kernel(
    const float* __restrict__ X, const float* __restrict__ W,
    float* __restrict__ Y, int do_norm, float scale) {
  const int h = blockIdx.x;
  const int n = blockIdx.y;
  const int tid = threadIdx.x;
  const int c = h * DK + tid;
  float y = 0.f;
#pragma unroll
  for (int i = 0; i < 4; i++) {
    int nn = n - 3 + i;
    if (nn >= 0) y = fmaf(X[(size_t)nn * PROJ + c], W[c * 4 + i], y);
  }
  y = y / (1.f + expf(-y));  // SiLU
  __shared__ float red[4];
  if (do_norm) {
    float ss = y * y;
#pragma unroll
    for (int o = 16; o > 0; o >>= 1) ss += __shfl_xor_sync(0xffffffffu, ss, o);
    if ((tid & 31) == 0) red[tid >> 5] = ss;
    __syncthreads();
    float tot = red[0] + red[1] + red[2] + red[3];
    y *= rsqrtf(tot + 1e-6f) * scale;
  }
  Y[(size_t)n * PROJ + c] = y;
}

// -------- exp(g) = exp(-exp(A_log[h]) * softplus(f + dt_bias)), in place --------
__global__ void __launch_bounds__(256) gate_decay_kernel(
    float* __restrict__ F, const float* __restrict__ dt_bias,
    const float* __restrict__ A_log) {
  const int idx = blockIdx.x * 256 + threadIdx.x;
  const int c = idx & (PROJ - 1);
  const int h = c >> 7;
  float x = F[idx] + dt_bias[c];
  float sp = (x > 20.f) ? x : log1pf(expf(x));
  F[idx] = expf(-expf(A_log[h]) * sp);
}

// ---------------- sequential delta-rule scan ----------------
// grid: 32 heads x 4 v-slices = 128 blocks, 256 threads.
// thread (vloc = tid>>3 in [0,32), kc = tid&7 in [0,8)) owns S[kc*16 + j][v], j<16.
// Inputs double-buffered in shared with register prefetch; k/q/eg stored in a
// transposed-swizzled layout so inner-loop LDS are pure broadcasts.
__global__ void __launch_bounds__(256, 1) scan_kernel(
    const float* __restrict__ Q, const float* __restrict__ K,
    const float* __restrict__ V, const float* __restrict__ EG,
    const float* __restrict__ BRAW, float* __restrict__ O) {
  const int h = blockIdx.x >> 2;
  const int vbase = (blockIdx.x & 3) << 5;
  const int tid = threadIdx.x;
  const int vloc = tid >> 3;
  const int kc = tid & 7;

  __shared__ float k_sh[2][128], q_sh[2][128], e_sh[2][128];
  __shared__ float v_sh[2][32];
  __shared__ float b_sh[2];

  float S[16];
#pragma unroll
  for (int j = 0; j < 16; j++) S[j] = 0.f;

  const size_t hb = (size_t)h * DK;
  float pk = 0.f, pe = 0.f, pq = 0.f, pv = 0.f, pb = 0.f;

  // prefetch t = 0
  if (tid < 128) {
    pk = K[hb + tid];
    pe = EG[hb + tid];
  } else {
    int u = tid - 128;
    pq = Q[hb + u];
    if (u < 32) pv = V[hb + vbase + u];
    if (u == 127) pb = BRAW[h];
  }

  for (int t = 0; t < NSEQ; t++) {
    const int buf = t & 1;
    if (tid < 128) {
      int sw = ((tid & 15) << 3) | (tid >> 4);
      k_sh[buf][sw] = pk;
      e_sh[buf][sw] = pe;
    } else {
      int u = tid - 128;
      q_sh[buf][((u & 15) << 3) | (u >> 4)] = pq;
      if (u < 32) v_sh[buf][u] = pv;
      if (u == 127) b_sh[buf] = 1.f / (1.f + expf(-pb));
    }
    __syncthreads();

    if (t + 1 < NSEQ) {
      size_t off = (size_t)(t + 1) * PROJ + hb;
      if (tid < 128) {
        pk = K[off + tid];
        pe = EG[off + tid];
      } else {
        int u = tid - 128;
        pq = Q[off + u];
        if (u < 32) pv = V[off + vbase + u];
        if (u == 127) pb = BRAW[(size_t)(t + 1) * NH + h];
      }
    }

    float kreg[16];
    float kv0 = 0.f, kv1 = 0.f;
#pragma unroll
    for (int j = 0; j < 16; j++) {
      float e = e_sh[buf][(j << 3) | kc];
      float kk = k_sh[buf][(j << 3) | kc];
      kreg[j] = kk;
      float s = S[j] * e;
      S[j] = s;
      if (j & 1) kv1 = fmaf(kk, s, kv1); else kv0 = fmaf(kk, s, kv0);
    }
    float kv = kv0 + kv1;
    kv += __shfl_xor_sync(0xffffffffu, kv, 1);
    kv += __shfl_xor_sync(0xffffffffu, kv, 2);
    kv += __shfl_xor_sync(0xffffffffu, kv, 4);

    const float delta = (v_sh[buf][vloc] - kv) * b_sh[buf];

    float o0 = 0.f, o1 = 0.f;
#pragma unroll
    for (int j = 0; j < 16; j++) {
      float q = q_sh[buf][(j << 3) | kc];
      float s = fmaf(kreg[j], delta, S[j]);
      S[j] = s;
      if (j & 1) o1 = fmaf(q, s, o1); else o0 = fmaf(q, s, o0);
    }
    float o = o0 + o1;
    o += __shfl_xor_sync(0xffffffffu, o, 1);
    o += __shfl_xor_sync(0xffffffffu, o, 2);
    o += __shfl_xor_sync(0xffffffffu, o, 4);
    if (kc == 0) O[(size_t)t * PROJ + hb + vbase + vloc] = o;
    __syncthreads();
  }
}

// -------- gated RMSNorm: core = rms(core) * onorm_w * sigmoid(gate), in place --------
__global__ void __launch_bounds__(128) out_gate_kernel(
    float* __restrict__ CORE, const float* __restrict__ GATE,
    const float* __restrict__ onorm_w) {
  const int h = blockIdx.x;
  const int n = blockIdx.y;
  const int tid = threadIdx.x;
  const size_t idx = (size_t)n * PROJ + h * DK + tid;
  float cv = CORE[idx];
  float ss = cv * cv;
#pragma unroll
  for (int o = 16; o > 0; o >>= 1) ss += __shfl_xor_sync(0xffffffffu, ss, o);
  __shared__ float red[4];
  if ((tid & 31) == 0) red[tid >> 5] = ss;
  __syncthreads();
  float tot = red[0] + red[1] + red[2] + red[3];
  float r = rsqrtf(tot * (1.f / 128.f) + 1e-5f);
  float gt = GATE[idx];
  CORE[idx] = cv * r * onorm_w[tid] / (1.f + expf(-gt));
}

// ---------------- launch ----------------
extern "C" void kernel_launch(void* const* d_in, const int* in_sizes, int n_in,
                              void* d_out, int out_size) {
  const float* hs      = (const float*)d_in[0];
  const float* Wq      = (const float*)d_in[1];
  const float* Wk      = (const float*)d_in[2];
  const float* Wv      = (const float*)d_in[3];
  const float* conv_q  = (const float*)d_in[4];
  const float* conv_k  = (const float*)d_in[5];
  const float* conv_v  = (const float*)d_in[6];
  const float* Wfa     = (const float*)d_in[7];
  const float* Wfb     = (const float*)d_in[8];
  const float* dt_bias = (const float*)d_in[9];
  const float* Wb      = (const float*)d_in[10];
  const float* A_log   = (const float*)d_in[11];
  const float* Wga     = (const float*)d_in[12];
  const float* Wgb     = (const float*)d_in[13];
  const float* onorm_w = (const float*)d_in[14];
  const float* Wo      = (const float*)d_in[15];
  float* out = (float*)d_out;

  float *Qp, *Kp, *Vp, *Qc, *Kc, *Vc, *F, *GATE, *CORE, *FA, *GA, *BRAW;
  cudaGetSymbolAddress((void**)&Qp,   g_Qp);
  cudaGetSymbolAddress((void**)&Kp,   g_Kp);
  cudaGetSymbolAddress((void**)&Vp,   g_Vp);
  cudaGetSymbolAddress((void**)&Qc,   g_Qc);
  cudaGetSymbolAddress((void**)&Kc,   g_Kc);
  cudaGetSymbolAddress((void**)&Vc,   g_Vc);
  cudaGetSymbolAddress((void**)&F,    g_F);
  cudaGetSymbolAddress((void**)&GATE, g_GATE);
  cudaGetSymbolAddress((void**)&CORE, g_CORE);
  cudaGetSymbolAddress((void**)&FA,   g_FA);
  cudaGetSymbolAddress((void**)&GA,   g_GA);
  cudaGetSymbolAddress((void**)&BRAW, g_BRAW);

  const dim3 blk256(256);
  const dim3 gProj(PROJ / 128, NSEQ / 128);   // (32,16)
  const dim3 gLow(1, NSEQ / 128);             // N<=128
  const dim3 gOut(HID / 128, NSEQ / 128);     // (16,16)

  // projections
  gemm_nt_kernel<<<gProj, blk256>>>(hs, Wq, Qp, NSEQ, PROJ, HID);
  gemm_nt_kernel<<<gProj, blk256>>>(hs, Wk, Kp, NSEQ, PROJ, HID);
  gemm_nt_kernel<<<gProj, blk256>>>(hs, Wv, Vp, NSEQ, PROJ, HID);
  gemm_nt_kernel<<<gLow,  blk256>>>(hs, Wfa, FA, NSEQ, DK, HID);
  gemm_nt_kernel<<<gLow,  blk256>>>(hs, Wga, GA, NSEQ, DK, HID);
  gemm_nt_kernel<<<gLow,  blk256>>>(hs, Wb, BRAW, NSEQ, NH, HID);
  gemm_nt_kernel<<<gProj, blk256>>>(FA, Wfb, F,    NSEQ, PROJ, DK);
  gemm_nt_kernel<<<gProj, blk256>>>(GA, Wgb, GATE, NSEQ, PROJ, DK);

  // conv + silu (+ l2 norm for q,k)
  dim3 gConv(NH, NSEQ);
  conv_silu_kernel<<<gConv, 128>>>(Qp, conv_q, Qc, 1, QSCALE);
  conv_silu_kernel<<<gConv, 128>>>(Kp, conv_k, Kc, 1, 1.0f);
  conv_silu_kernel<<<gConv, 128>>>(Vp, conv_v, Vc, 0, 1.0f);

  // exp(g) in place over F
  gate_decay_kernel<<<(NSEQ * PROJ) / 256, 256>>>(F, dt_bias, A_log);

  // recurrent scan
  scan_kernel<<<NH * 4, 256>>>(Qc, Kc, Vc, F, BRAW, CORE);

  // gated rmsnorm (in place over CORE)
  out_gate_kernel<<<gConv, 128>>>(CORE, GATE, onorm_w);

  // output projection
  gemm_nt_kernel<<<gOut, blk256>>>(CORE, Wo, out, NSEQ, HID, PROJ);
}

// round 5
// speedup vs baseline: 1.7198x; 1.7198x over previous
#include <cuda_runtime.h>
#include <cuda_bf16.h>
#include <math.h>
#include <stdint.h>

#define NSEQ 2048
#define HID  2048
#define NH   32
#define DK   128
#define PROJ 4096
#define QSCALE 0.08838834764831843f   // 128^-0.5

#define NS_COMB   288                   // Wfa(128) + Wga(128) + Wb(32)
#define NS_PAD    384

// ---- GEMM tiling ----
#define BM 128
#define BN 128
#define BK 32
#define ASTR 40                          // smem row stride in bf16 elems (80B) - conflict free
#define MATB (128 * ASTR * 2)            // 10240 bytes per matrix tile
#define STAGEB (4 * MATB)                // Ah,Al,Bh,Bl = 40960 bytes
#define NSTG 3
#define SMEMB (NSTG * STAGEB)            // 122880 bytes

// ---------------- scratch (device globals; no allocation allowed) ----------------
__device__ __align__(256) float g_Qp[NSEQ * PROJ];
__device__ __align__(256) float g_Kp[NSEQ * PROJ];
__device__ __align__(256) float g_Vp[NSEQ * PROJ];
__device__ __align__(256) float g_Qc[NSEQ * PROJ];
__device__ __align__(256) float g_Kc[NSEQ * PROJ];
__device__ __align__(256) float g_Vc[NSEQ * PROJ];
__device__ __align__(256) float g_F[NSEQ * PROJ];
__device__ __align__(256) float g_GATE[NSEQ * PROJ];
__device__ __align__(256) float g_CORE[NSEQ * PROJ];
__device__ __align__(256) float g_COMB[NSEQ * NS_COMB];

__device__ __align__(256) __nv_bfloat16 g_hsh[NSEQ * HID];
__device__ __align__(256) __nv_bfloat16 g_hsl[NSEQ * HID];
__device__ __align__(256) __nv_bfloat16 g_Wqh[PROJ * HID];
__device__ __align__(256) __nv_bfloat16 g_Wql[PROJ * HID];
__device__ __align__(256) __nv_bfloat16 g_Wkh[PROJ * HID];
__device__ __align__(256) __nv_bfloat16 g_Wkl[PROJ * HID];
__device__ __align__(256) __nv_bfloat16 g_Wvh[PROJ * HID];
__device__ __align__(256) __nv_bfloat16 g_Wvl[PROJ * HID];
__device__ __align__(256) __nv_bfloat16 g_Woh[HID * PROJ];
__device__ __align__(256) __nv_bfloat16 g_Wol[HID * PROJ];
__device__ __align__(256) __nv_bfloat16 g_Wfbh[PROJ * DK];
__device__ __align__(256) __nv_bfloat16 g_Wfbl[PROJ * DK];
__device__ __align__(256) __nv_bfloat16 g_Wgbh[PROJ * DK];
__device__ __align__(256) __nv_bfloat16 g_Wgbl[PROJ * DK];
__device__ __align__(256) __nv_bfloat16 g_WSh[NS_PAD * HID];
__device__ __align__(256) __nv_bfloat16 g_WSl[NS_PAD * HID];
__device__ __align__(256) __nv_bfloat16 g_FAh[NSEQ * DK];
__device__ __align__(256) __nv_bfloat16 g_FAl[NSEQ * DK];
__device__ __align__(256) __nv_bfloat16 g_GAh[NSEQ * DK];
__device__ __align__(256) __nv_bfloat16 g_GAl[NSEQ * DK];
__device__ __align__(256) __nv_bfloat16 g_COREh[NSEQ * PROJ];
__device__ __align__(256) __nv_bfloat16 g_COREl[NSEQ * PROJ];

// ============================ helpers (sm_80-portable PTX only) ============================
__device__ __forceinline__ uint32_t smem_u32(const void* p) {
  return (uint32_t)__cvta_generic_to_shared(p);
}
__device__ __forceinline__ void cp_async16(uint32_t dst, const void* src) {
  asm volatile("cp.async.cg.shared.global [%0], [%1], 16;" :: "r"(dst), "l"(src) : "memory");
}
__device__ __forceinline__ void cp_commit() {
  asm volatile("cp.async.commit_group;" ::: "memory");
}
template<int N> __device__ __forceinline__ void cp_wait() {
  asm volatile("cp.async.wait_group %0;" :: "n"(N) : "memory");
}
__device__ __forceinline__ uint32_t lds32(uint32_t a) {
  uint32_t v;
  asm volatile("ld.shared.b32 %0, [%1];" : "=r"(v) : "r"(a));
  return v;
}
__device__ __forceinline__ void mma16816(float* c, const uint32_t* a, const uint32_t* b) {
  asm volatile(
      "mma.sync.aligned.m16n8k16.row.col.f32.bf16.bf16.f32 "
      "{%0,%1,%2,%3}, {%4,%5,%6,%7}, {%8,%9}, {%0,%1,%2,%3};"
      : "+f"(c[0]), "+f"(c[1]), "+f"(c[2]), "+f"(c[3])
      : "r"(a[0]), "r"(a[1]), "r"(a[2]), "r"(a[3]), "r"(b[0]), "r"(b[1]));
}

// ======================= bf16 hi/lo split GEMM (mma.sync) =======================
// C[M,Nn] = A[M,K] * B[Nn,K]^T with A,B given as bf16 (hi,lo) pairs.
// 3 passes: Ah*Bh + Ah*Bl + Al*Bh. M multiple of 128; N arbitrary (B buffer
// must be row-padded to the tile); K multiple of 32.
__device__ __forceinline__ void ld_stage(uint32_t sb, int slot, int kt, int tid,
                                         const char* a_h, const char* a_l,
                                         const char* b_h, const char* b_l,
                                         size_t kbytes) {
  const uint32_t st = sb + (uint32_t)slot * STAGEB;
  const int row = tid >> 1;
  const int c0 = (tid & 1) * 32;       // byte offset within the 64B row chunk
  const uint32_t so = (uint32_t)(row * (ASTR * 2) + c0);
  const size_t go = (size_t)row * kbytes + (size_t)kt * (BK * 2) + (size_t)c0;
  cp_async16(st + so,                a_h + go);
  cp_async16(st + so + 16,           a_h + go + 16);
  cp_async16(st + MATB + so,         a_l + go);
  cp_async16(st + MATB + so + 16,    a_l + go + 16);
  cp_async16(st + 2 * MATB + so,     b_h + go);
  cp_async16(st + 2 * MATB + so + 16, b_h + go + 16);
  cp_async16(st + 3 * MATB + so,     b_l + go);
  cp_async16(st + 3 * MATB + so + 16, b_l + go + 16);
  cp_commit();
}

__global__ void __launch_bounds__(256, 1) gemm_bf16s(
    const __nv_bfloat16* __restrict__ Ah, const __nv_bfloat16* __restrict__ Al,
    const __nv_bfloat16* __restrict__ Bh, const __nv_bfloat16* __restrict__ Bl,
    float* __restrict__ C, int M, int Nn, int K) {
  extern __shared__ char sm[];
  const int tid = threadIdx.x;
  const int bm = blockIdx.y * BM, bn = blockIdx.x * BN;
  const uint32_t sb = smem_u32(sm);

  const int lane = tid & 31, warp = tid >> 5;
  const int gid = lane >> 2, tig = lane & 3;
  const int wR = warp >> 2;            // 0..1  (M direction, 64 rows each)
  const int wC = warp & 3;             // 0..3  (N direction, 32 cols each)

  const size_t kbytes = (size_t)K * 2;
  const char* a_h = (const char*)Ah + (size_t)bm * kbytes;
  const char* a_l = (const char*)Al + (size_t)bm * kbytes;
  const char* b_h = (const char*)Bh + (size_t)bn * kbytes;
  const char* b_l = (const char*)Bl + (size_t)bn * kbytes;

  float acc[4][4][4];
#pragma unroll
  for (int i = 0; i < 4; i++)
#pragma unroll
    for (int j = 0; j < 4; j++)
#pragma unroll
      for (int r = 0; r < 4; r++) acc[i][j][r] = 0.f;

  const int KT = K / BK;
  for (int s = 0; s < NSTG; s++)
    if (s < KT) ld_stage(sb, s, s, tid, a_h, a_l, b_h, b_l, kbytes);

  // fragment smem base offsets (bytes), per thread
  const uint32_t aRowBase = (uint32_t)((wR * 64 + gid) * (ASTR * 2) + tig * 4);
  const uint32_t bRowBase = (uint32_t)((wC * 32 + gid) * (ASTR * 2) + tig * 4);

  for (int kt = 0; kt < KT; kt++) {
    const int slot = kt % NSTG;
    const int pend = KT - 1 - kt;
    if (pend >= 2) cp_wait<2>(); else if (pend == 1) cp_wait<1>(); else cp_wait<0>();
    __syncthreads();

    const uint32_t st = sb + (uint32_t)slot * STAGEB;
#pragma unroll
    for (int kk = 0; kk < 2; kk++) {
      const uint32_t kb = (uint32_t)(kk * 32);   // 16 bf16 = 32 bytes
      uint32_t afh[4][4], afl[4][4];
#pragma unroll
      for (int mt = 0; mt < 4; mt++) {
        const uint32_t r0 = st + aRowBase + (uint32_t)(mt * 16 * (ASTR * 2)) + kb;
        afh[mt][0] = lds32(r0);
        afh[mt][1] = lds32(r0 + 8 * (ASTR * 2));
        afh[mt][2] = lds32(r0 + 16);
        afh[mt][3] = lds32(r0 + 8 * (ASTR * 2) + 16);
        const uint32_t r1 = r0 + MATB;
        afl[mt][0] = lds32(r1);
        afl[mt][1] = lds32(r1 + 8 * (ASTR * 2));
        afl[mt][2] = lds32(r1 + 16);
        afl[mt][3] = lds32(r1 + 8 * (ASTR * 2) + 16);
      }
      uint32_t bfh[4][2], bfl[4][2];
#pragma unroll
      for (int nt = 0; nt < 4; nt++) {
        const uint32_t r0 = st + 2 * MATB + bRowBase + (uint32_t)(nt * 8 * (ASTR * 2)) + kb;
        bfh[nt][0] = lds32(r0);
        bfh[nt][1] = lds32(r0 + 16);
        const uint32_t r1 = r0 + MATB;
        bfl[nt][0] = lds32(r1);
        bfl[nt][1] = lds32(r1 + 16);
      }
#pragma unroll
      for (int mt = 0; mt < 4; mt++)
#pragma unroll
        for (int nt = 0; nt < 4; nt++) {
          mma16816(acc[mt][nt], afh[mt], bfh[nt]);
          mma16816(acc[mt][nt], afh[mt], bfl[nt]);
          mma16816(acc[mt][nt], afl[mt], bfh[nt]);
        }
    }
    __syncthreads();
    const int nk = kt + NSTG;
    if (nk < KT) ld_stage(sb, slot, nk, tid, a_h, a_l, b_h, b_l, kbytes);
  }

  // epilogue
#pragma unroll
  for (int mt = 0; mt < 4; mt++) {
    const int row = bm + wR * 64 + mt * 16 + gid;
#pragma unroll
    for (int nt = 0; nt < 4; nt++) {
      const int col = bn + wC * 32 + nt * 8 + tig * 2;
      if (col < Nn) {
        float2 v0 = make_float2(acc[mt][nt][0], acc[mt][nt][1]);
        float2 v1 = make_float2(acc[mt][nt][2], acc[mt][nt][3]);
        *reinterpret_cast<float2*>(C + (size_t)row * Nn + col) = v0;
        *reinterpret_cast<float2*>(C + (size_t)(row + 8) * Nn + col) = v1;
      }
    }
  }
}

// ======================= fp32 -> bf16 hi/lo split =======================
__global__ void __launch_bounds__(256) split_bf16_kernel(
    const float* __restrict__ src, int srcStride, int cols,
    __nv_bfloat16* __restrict__ hi, __nv_bfloat16* __restrict__ lo, int total) {
  int idx = blockIdx.x * 256 + threadIdx.x;
  if (idx >= total) return;
  int r = idx / cols, c = idx - r * cols;
  float x = src[(size_t)r * srcStride + c];
  __nv_bfloat16 h = __float2bfloat16_rn(x);
  float rem = x - __bfloat162float(h);
  hi[idx] = h;
  lo[idx] = __float2bfloat16_rn(rem);
}

// stacked small-weight matrix [Wfa;Wga;Wb;zeros] -> bf16 hi/lo [384, HID]
__global__ void __launch_bounds__(256) ws_build_kernel(
    const float* __restrict__ Wfa, const float* __restrict__ Wga,
    const float* __restrict__ Wb,
    __nv_bfloat16* __restrict__ hi, __nv_bfloat16* __restrict__ lo) {
  int idx = blockIdx.x * 256 + threadIdx.x;
  if (idx >= NS_PAD * HID) return;
  int r = idx / HID, c = idx - r * HID;
  float x = 0.f;
  if (r < 128) x = Wfa[r * HID + c];
  else if (r < 256) x = Wga[(r - 128) * HID + c];
  else if (r < NS_COMB) x = Wb[(r - 256) * HID + c];
  __nv_bfloat16 h = __float2bfloat16_rn(x);
  hi[idx] = h;
  lo[idx] = __float2bfloat16_rn(x - __bfloat162float(h));
}

// -------- depthwise causal conv(K=4) + SiLU, optional per-(n,h) L2 norm --------
__global__ void __launch_bounds__(128) conv_silu_kernel(
    const float* __restrict__ X, const float* __restrict__ W,
    float* __restrict__ Y, int do_norm, float scale) {
  const int h = blockIdx.x;
  const int n = blockIdx.y;
  const int tid = threadIdx.x;
  const int c = h * DK + tid;
  float y = 0.f;
#pragma unroll
  for (int i = 0; i < 4; i++) {
    int nn = n - 3 + i;
    if (nn >= 0) y = fmaf(X[(size_t)nn * PROJ + c], W[c * 4 + i], y);
  }
  y = y / (1.f + expf(-y));  // SiLU
  __shared__ float red[4];
  if (do_norm) {
    float ss = y * y;
#pragma unroll
    for (int o = 16; o > 0; o >>= 1) ss += __shfl_xor_sync(0xffffffffu, ss, o);
    if ((tid & 31) == 0) red[tid >> 5] = ss;
    __syncthreads();
    float tot = red[0] + red[1] + red[2] + red[3];
    y *= rsqrtf(tot + 1e-6f) * scale;
  }
  Y[(size_t)n * PROJ + c] = y;
}

// -------- exp(g) = exp(-exp(A_log[h]) * softplus(f + dt_bias)), in place --------
__global__ void __launch_bounds__(256) gate_decay_kernel(
    float* __restrict__ F, const float* __restrict__ dt_bias,
    const float* __restrict__ A_log) {
  const int idx = blockIdx.x * 256 + threadIdx.x;
  const int c = idx & (PROJ - 1);
  const int h = c >> 7;
  float x = F[idx] + dt_bias[c];
  float sp = (x > 20.f) ? x : log1pf(expf(x));
  F[idx] = expf(-expf(A_log[h]) * sp);
}

// ---------------- sequential delta-rule scan ----------------
__global__ void __launch_bounds__(256, 1) scan_kernel(
    const float* __restrict__ Q, const float* __restrict__ K,
    const float* __restrict__ V, const float* __restrict__ EG,
    const float* __restrict__ BRAW, int bstride, float* __restrict__ O) {
  const int h = blockIdx.x >> 2;
  const int vbase = (blockIdx.x & 3) << 5;
  const int tid = threadIdx.x;
  const int vloc = tid >> 3;
  const int kc = tid & 7;

  __shared__ float k_sh[2][128], q_sh[2][128], e_sh[2][128];
  __shared__ float v_sh[2][32];
  __shared__ float b_sh[2];

  float S[16];
#pragma unroll
  for (int j = 0; j < 16; j++) S[j] = 0.f;

  const size_t hb = (size_t)h * DK;
  float pk = 0.f, pe = 0.f, pq = 0.f, pv = 0.f, pb = 0.f;

  if (tid < 128) {
    pk = K[hb + tid];
    pe = EG[hb + tid];
  } else {
    int u = tid - 128;
    pq = Q[hb + u];
    if (u < 32) pv = V[hb + vbase + u];
    if (u == 127) pb = BRAW[h];
  }

  for (int t = 0; t < NSEQ; t++) {
    const int buf = t & 1;
    if (tid < 128) {
      int sw = ((tid & 15) << 3) | (tid >> 4);
      k_sh[buf][sw] = pk;
      e_sh[buf][sw] = pe;
    } else {
      int u = tid - 128;
      q_sh[buf][((u & 15) << 3) | (u >> 4)] = pq;
      if (u < 32) v_sh[buf][u] = pv;
      if (u == 127) b_sh[buf] = 1.f / (1.f + expf(-pb));
    }
    __syncthreads();

    if (t + 1 < NSEQ) {
      size_t off = (size_t)(t + 1) * PROJ + hb;
      if (tid < 128) {
        pk = K[off + tid];
        pe = EG[off + tid];
      } else {
        int u = tid - 128;
        pq = Q[off + u];
        if (u < 32) pv = V[off + vbase + u];
        if (u == 127) pb = BRAW[(size_t)(t + 1) * bstride + h];
      }
    }

    float kreg[16];
    float kv0 = 0.f, kv1 = 0.f;
#pragma unroll
    for (int j = 0; j < 16; j++) {
      float e = e_sh[buf][(j << 3) | kc];
      float kk = k_sh[buf][(j << 3) | kc];
      kreg[j] = kk;
      float s = S[j] * e;
      S[j] = s;
      if (j & 1) kv1 = fmaf(kk, s, kv1); else kv0 = fmaf(kk, s, kv0);
    }
    float kv = kv0 + kv1;
    kv += __shfl_xor_sync(0xffffffffu, kv, 1);
    kv += __shfl_xor_sync(0xffffffffu, kv, 2);
    kv += __shfl_xor_sync(0xffffffffu, kv, 4);

    const float delta = (v_sh[buf][vloc] - kv) * b_sh[buf];

    float o0 = 0.f, o1 = 0.f;
#pragma unroll
    for (int j = 0; j < 16; j++) {
      float q = q_sh[buf][(j << 3) | kc];
      float s = fmaf(kreg[j], delta, S[j]);
      S[j] = s;
      if (j & 1) o1 = fmaf(q, s, o1); else o0 = fmaf(q, s, o0);
    }
    float o = o0 + o1;
    o += __shfl_xor_sync(0xffffffffu, o, 1);
    o += __shfl_xor_sync(0xffffffffu, o, 2);
    o += __shfl_xor_sync(0xffffffffu, o, 4);
    if (kc == 0) O[(size_t)t * PROJ + hb + vbase + vloc] = o;
    __syncthreads();
  }
}

// -------- gated RMSNorm: core = rms(core) * onorm_w * sigmoid(gate), in place --------
__global__ void __launch_bounds__(128) out_gate_kernel(
    float* __restrict__ CORE, const float* __restrict__ GATE,
    const float* __restrict__ onorm_w) {
  const int h = blockIdx.x;
  const int n = blockIdx.y;
  const int tid = threadIdx.x;
  const size_t idx = (size_t)n * PROJ + h * DK + tid;
  float cv = CORE[idx];
  float ss = cv * cv;
#pragma unroll
  for (int o = 16; o > 0; o >>= 1) ss += __shfl_xor_sync(0xffffffffu, ss, o);
  __shared__ float red[4];
  if ((tid & 31) == 0) red[tid >> 5] = ss;
  __syncthreads();
  float tot = red[0] + red[1] + red[2] + red[3];
  float r = rsqrtf(tot * (1.f / 128.f) + 1e-5f);
  float gt = GATE[idx];
  CORE[idx] = cv * r * onorm_w[tid] / (1.f + expf(-gt));
}

// ---------------- launch ----------------
extern "C" void kernel_launch(void* const* d_in, const int* in_sizes, int n_in,
                              void* d_out, int out_size) {
  const float* hs      = (const float*)d_in[0];
  const float* Wq      = (const float*)d_in[1];
  const float* Wk      = (const float*)d_in[2];
  const float* Wv      = (const float*)d_in[3];
  const float* conv_q  = (const float*)d_in[4];
  const float* conv_k  = (const float*)d_in[5];
  const float* conv_v  = (const float*)d_in[6];
  const float* Wfa     = (const float*)d_in[7];
  const float* Wfb     = (const float*)d_in[8];
  const float* dt_bias = (const float*)d_in[9];
  const float* Wb      = (const float*)d_in[10];
  const float* A_log   = (const float*)d_in[11];
  const float* Wga     = (const float*)d_in[12];
  const float* Wgb     = (const float*)d_in[13];
  const float* onorm_w = (const float*)d_in[14];
  const float* Wo      = (const float*)d_in[15];
  float* out = (float*)d_out;

  float *Qp, *Kp, *Vp, *Qc, *Kc, *Vc, *F, *GATE, *CORE, *COMB;
  __nv_bfloat16 *hsh, *hsl, *Wqh, *Wql, *Wkh, *Wkl, *Wvh, *Wvl, *Woh, *Wol;
  __nv_bfloat16 *Wfbh, *Wfbl, *Wgbh, *Wgbl, *WSh, *WSl;
  __nv_bfloat16 *FAh, *FAl, *GAh, *GAl, *COREh, *COREl;
  cudaGetSymbolAddress((void**)&Qp,    g_Qp);
  cudaGetSymbolAddress((void**)&Kp,    g_Kp);
  cudaGetSymbolAddress((void**)&Vp,    g_Vp);
  cudaGetSymbolAddress((void**)&Qc,    g_Qc);
  cudaGetSymbolAddress((void**)&Kc,    g_Kc);
  cudaGetSymbolAddress((void**)&Vc,    g_Vc);
  cudaGetSymbolAddress((void**)&F,     g_F);
  cudaGetSymbolAddress((void**)&GATE,  g_GATE);
  cudaGetSymbolAddress((void**)&CORE,  g_CORE);
  cudaGetSymbolAddress((void**)&COMB,  g_COMB);
  cudaGetSymbolAddress((void**)&hsh,   g_hsh);
  cudaGetSymbolAddress((void**)&hsl,   g_hsl);
  cudaGetSymbolAddress((void**)&Wqh,   g_Wqh);
  cudaGetSymbolAddress((void**)&Wql,   g_Wql);
  cudaGetSymbolAddress((void**)&Wkh,   g_Wkh);
  cudaGetSymbolAddress((void**)&Wkl,   g_Wkl);
  cudaGetSymbolAddress((void**)&Wvh,   g_Wvh);
  cudaGetSymbolAddress((void**)&Wvl,   g_Wvl);
  cudaGetSymbolAddress((void**)&Woh,   g_Woh);
  cudaGetSymbolAddress((void**)&Wol,   g_Wol);
  cudaGetSymbolAddress((void**)&Wfbh,  g_Wfbh);
  cudaGetSymbolAddress((void**)&Wfbl,  g_Wfbl);
  cudaGetSymbolAddress((void**)&Wgbh,  g_Wgbh);
  cudaGetSymbolAddress((void**)&Wgbl,  g_Wgbl);
  cudaGetSymbolAddress((void**)&WSh,   g_WSh);
  cudaGetSymbolAddress((void**)&WSl,   g_WSl);
  cudaGetSymbolAddress((void**)&FAh,   g_FAh);
  cudaGetSymbolAddress((void**)&FAl,   g_FAl);
  cudaGetSymbolAddress((void**)&GAh,   g_GAh);
  cudaGetSymbolAddress((void**)&GAl,   g_GAl);
  cudaGetSymbolAddress((void**)&COREh, g_COREh);
  cudaGetSymbolAddress((void**)&COREl, g_COREl);

  cudaFuncSetAttribute(gemm_bf16s, cudaFuncAttributeMaxDynamicSharedMemorySize, SMEMB);

  // ---- split conversions ----
  int T;
  T = NSEQ * HID;
  split_bf16_kernel<<<(T + 255) / 256, 256>>>(hs, HID, HID, hsh, hsl, T);
  T = PROJ * HID;
  split_bf16_kernel<<<(T + 255) / 256, 256>>>(Wq, HID, HID, Wqh, Wql, T);
  split_bf16_kernel<<<(T + 255) / 256, 256>>>(Wk, HID, HID, Wkh, Wkl, T);
  split_bf16_kernel<<<(T + 255) / 256, 256>>>(Wv, HID, HID, Wvh, Wvl, T);
  T = HID * PROJ;
  split_bf16_kernel<<<(T + 255) / 256, 256>>>(Wo, PROJ, PROJ, Woh, Wol, T);
  T = PROJ * DK;
  split_bf16_kernel<<<(T + 255) / 256, 256>>>(Wfb, DK, DK, Wfbh, Wfbl, T);
  split_bf16_kernel<<<(T + 255) / 256, 256>>>(Wgb, DK, DK, Wgbh, Wgbl, T);
  ws_build_kernel<<<(NS_PAD * HID + 255) / 256, 256>>>(Wfa, Wga, Wb, WSh, WSl);

  // ---- tensor-core GEMMs: QKV + fused small (FA|GA|beta) ----
  gemm_bf16s<<<dim3(PROJ / 128, NSEQ / 128), 256, SMEMB>>>(hsh, hsl, Wqh, Wql, Qp, NSEQ, PROJ, HID);
  gemm_bf16s<<<dim3(PROJ / 128, NSEQ / 128), 256, SMEMB>>>(hsh, hsl, Wkh, Wkl, Kp, NSEQ, PROJ, HID);
  gemm_bf16s<<<dim3(PROJ / 128, NSEQ / 128), 256, SMEMB>>>(hsh, hsl, Wvh, Wvl, Vp, NSEQ, PROJ, HID);
  gemm_bf16s<<<dim3(3, NSEQ / 128), 256, SMEMB>>>(hsh, hsl, WSh, WSl, COMB, NSEQ, NS_COMB, HID);

  // ---- conv + silu (+ l2 norm for q,k) ----
  dim3 gConv(NH, NSEQ);
  conv_silu_kernel<<<gConv, 128>>>(Qp, conv_q, Qc, 1, QSCALE);
  conv_silu_kernel<<<gConv, 128>>>(Kp, conv_k, Kc, 1, 1.0f);
  conv_silu_kernel<<<gConv, 128>>>(Vp, conv_v, Vc, 0, 1.0f);

  // ---- low-rank second projections (K=128, tensor core) ----
  T = NSEQ * DK;
  split_bf16_kernel<<<(T + 255) / 256, 256>>>(COMB, NS_COMB, DK, FAh, FAl, T);
  split_bf16_kernel<<<(T + 255) / 256, 256>>>(COMB + DK, NS_COMB, DK, GAh, GAl, T);
  gemm_bf16s<<<dim3(PROJ / 128, NSEQ / 128), 256, SMEMB>>>(FAh, FAl, Wfbh, Wfbl, F, NSEQ, PROJ, DK);
  gemm_bf16s<<<dim3(PROJ / 128, NSEQ / 128), 256, SMEMB>>>(GAh, GAl, Wgbh, Wgbl, GATE, NSEQ, PROJ, DK);

  // ---- decay gate ----
  gate_decay_kernel<<<(NSEQ * PROJ) / 256, 256>>>(F, dt_bias, A_log);

  // ---- recurrent scan ----
  scan_kernel<<<NH * 4, 256>>>(Qc, Kc, Vc, F, COMB + 256, NS_COMB, CORE);

  // ---- gated rmsnorm ----
  out_gate_kernel<<<gConv, 128>>>(CORE, GATE, onorm_w);

  // ---- output projection ----
  T = NSEQ * PROJ;
  split_bf16_kernel<<<(T + 255) / 256, 256>>>(CORE, PROJ, PROJ, COREh, COREl, T);
  gemm_bf16s<<<dim3(HID / 128, NSEQ / 128), 256, SMEMB>>>(COREh, COREl, Woh, Wol, out, NSEQ, HID, PROJ);
}

// round 6
// speedup vs baseline: 2.0301x; 1.1805x over previous
#include <cuda_runtime.h>
#include <cuda_bf16.h>
#include <math.h>
#include <stdint.h>

#define NSEQ 2048
#define HID  2048
#define NH   32
#define DK   128
#define PROJ 4096
#define QKVN (3 * PROJ)                  // fused QKV output width = 12288
#define QSCALE 0.08838834764831843f     // 128^-0.5

#define NS_COMB   288                    // Wfa(128) + Wga(128) + Wb(32)
#define NS_PAD    384

// ---- GEMM tiling ----
#define BM 128
#define BN 128
#define BK 64
#define MATB   (128 * 128)               // one matrix tile: 128 rows x 128B = 16KB
#define STAGEB (4 * MATB)                // Ah,Al,Bh,Bl = 64KB
#define NSTG   3
#define SMEMB  (NSTG * STAGEB)           // 192KB

// ---------------- scratch (device globals; no allocation allowed) ----------------
__device__ __align__(256) float g_QKVp[NSEQ * QKVN];
__device__ __align__(256) float g_Qc[NSEQ * PROJ];
__device__ __align__(256) float g_Kc[NSEQ * PROJ];
__device__ __align__(256) float g_Vc[NSEQ * PROJ];
__device__ __align__(256) float g_F[NSEQ * PROJ];
__device__ __align__(256) float g_GATE[NSEQ * PROJ];
__device__ __align__(256) float g_CORE[NSEQ * PROJ];
__device__ __align__(256) float g_COMB[NSEQ * NS_COMB];

__device__ __align__(256) __nv_bfloat16 g_hsh[NSEQ * HID];
__device__ __align__(256) __nv_bfloat16 g_hsl[NSEQ * HID];
__device__ __align__(256) __nv_bfloat16 g_Wqkvh[QKVN * HID];
__device__ __align__(256) __nv_bfloat16 g_Wqkvl[QKVN * HID];
__device__ __align__(256) __nv_bfloat16 g_Woh[HID * PROJ];
__device__ __align__(256) __nv_bfloat16 g_Wol[HID * PROJ];
__device__ __align__(256) __nv_bfloat16 g_Wfbh[PROJ * DK];
__device__ __align__(256) __nv_bfloat16 g_Wfbl[PROJ * DK];
__device__ __align__(256) __nv_bfloat16 g_Wgbh[PROJ * DK];
__device__ __align__(256) __nv_bfloat16 g_Wgbl[PROJ * DK];
__device__ __align__(256) __nv_bfloat16 g_WSh[NS_PAD * HID];
__device__ __align__(256) __nv_bfloat16 g_WSl[NS_PAD * HID];
__device__ __align__(256) __nv_bfloat16 g_FAh[NSEQ * DK];
__device__ __align__(256) __nv_bfloat16 g_FAl[NSEQ * DK];
__device__ __align__(256) __nv_bfloat16 g_GAh[NSEQ * DK];
__device__ __align__(256) __nv_bfloat16 g_GAl[NSEQ * DK];
__device__ __align__(256) __nv_bfloat16 g_COREh[NSEQ * PROJ];
__device__ __align__(256) __nv_bfloat16 g_COREl[NSEQ * PROJ];

// ============================ helpers (sm_80-portable PTX only) ============================
__device__ __forceinline__ uint32_t smem_u32(const void* p) {
  return (uint32_t)__cvta_generic_to_shared(p);
}
__device__ __forceinline__ void cp_async16(uint32_t dst, const void* src) {
  asm volatile("cp.async.cg.shared.global [%0], [%1], 16;" :: "r"(dst), "l"(src) : "memory");
}
__device__ __forceinline__ void cp_commit() {
  asm volatile("cp.async.commit_group;" ::: "memory");
}
template<int N> __device__ __forceinline__ void cp_wait() {
  asm volatile("cp.async.wait_group %0;" :: "n"(N) : "memory");
}
__device__ __forceinline__ void ldm_x4(uint32_t* r, uint32_t addr) {
  asm volatile("ldmatrix.sync.aligned.m8n8.x4.shared.b16 {%0,%1,%2,%3}, [%4];"
               : "=r"(r[0]), "=r"(r[1]), "=r"(r[2]), "=r"(r[3]) : "r"(addr));
}
__device__ __forceinline__ void mma16816(float* c, const uint32_t* a,
                                         uint32_t b0, uint32_t b1) {
  asm volatile(
      "mma.sync.aligned.m16n8k16.row.col.f32.bf16.bf16.f32 "
      "{%0,%1,%2,%3}, {%4,%5,%6,%7}, {%8,%9}, {%0,%1,%2,%3};"
      : "+f"(c[0]), "+f"(c[1]), "+f"(c[2]), "+f"(c[3])
      : "r"(a[0]), "r"(a[1]), "r"(a[2]), "r"(a[3]), "r"(b0), "r"(b1));
}

// ======================= bf16 hi/lo split GEMM (mma.sync + ldmatrix) =======================
// C[M,Nn] = A[M,K] * B[Nn,K]^T ; 3 passes Ah*Bh + Ah*Bl + Al*Bh.
// M,K multiples of tile; B buffer row-padded to 128-multiple rows; C has row stride ldc.
__device__ __forceinline__ void ld_stage(uint32_t sb, int slot, int kt, int tid,
                                         const char* a_h, const char* a_l,
                                         const char* b_h, const char* b_l,
                                         size_t kbytes) {
  const uint32_t st = sb + (uint32_t)slot * STAGEB;
#pragma unroll
  for (int i = 0; i < 4; i++) {
    const int chunk = i * 256 + tid;          // 0..1023
    const int row = chunk >> 3, kc = chunk & 7;
    const uint32_t so = (uint32_t)(row * 128 + ((kc ^ (row & 7)) << 4));
    const size_t go = (size_t)row * kbytes + (size_t)kt * 128 + (size_t)(kc << 4);
    cp_async16(st + so,            a_h + go);
    cp_async16(st + MATB + so,     a_l + go);
    cp_async16(st + 2 * MATB + so, b_h + go);
    cp_async16(st + 3 * MATB + so, b_l + go);
  }
  cp_commit();
}

__global__ void __launch_bounds__(256, 1) gemm_bf16s(
    const __nv_bfloat16* __restrict__ Ah, const __nv_bfloat16* __restrict__ Al,
    const __nv_bfloat16* __restrict__ Bh, const __nv_bfloat16* __restrict__ Bl,
    float* __restrict__ C, int Nn, int K, int ldc) {
  extern __shared__ char sm[];
  const int tid = threadIdx.x;
  const int bm = blockIdx.y * BM, bn = blockIdx.x * BN;
  const uint32_t sb = smem_u32(sm);

  const int lane = tid & 31, warp = tid >> 5;
  const int l16 = lane & 15, lh = lane >> 4;
  const int wR = warp >> 2;            // 0..1  (M, 64 rows)
  const int wC = warp & 3;             // 0..3  (N, 32 cols)

  const size_t kbytes = (size_t)K * 2;
  const char* a_h = (const char*)Ah + (size_t)bm * kbytes;
  const char* a_l = (const char*)Al + (size_t)bm * kbytes;
  const char* b_h = (const char*)Bh + (size_t)bn * kbytes;
  const char* b_l = (const char*)Bl + (size_t)bn * kbytes;

  float acc[4][4][4];
#pragma unroll
  for (int i = 0; i < 4; i++)
#pragma unroll
    for (int j = 0; j < 4; j++)
#pragma unroll
      for (int r = 0; r < 4; r++) acc[i][j][r] = 0.f;

  const int KT = K / BK;
  for (int s = 0; s < NSTG; s++)
    if (s < KT) ld_stage(sb, s, s, tid, a_h, a_l, b_h, b_l, kbytes);

#pragma unroll 1
  for (int kt = 0; kt < KT; kt++) {
    const int slot = kt % NSTG;
    int pend = KT - 1 - kt; if (pend > NSTG - 1) pend = NSTG - 1;
    if (pend >= 2) cp_wait<2>(); else if (pend == 1) cp_wait<1>(); else cp_wait<0>();
    __syncthreads();

    const uint32_t st = sb + (uint32_t)slot * STAGEB;
#pragma unroll
    for (int kk = 0; kk < 4; kk++) {
      const int kc = kk * 2 + lh;       // 16B chunk index within 128B row
      uint32_t afh[4][4], afl[4][4];
#pragma unroll
      for (int mt = 0; mt < 4; mt++) {
        const int arow = wR * 64 + mt * 16 + l16;
        const uint32_t ao = st + (uint32_t)(arow * 128 + ((kc ^ (arow & 7)) << 4));
        ldm_x4(afh[mt], ao);
        ldm_x4(afl[mt], ao + MATB);
      }
      uint32_t bfh[2][4], bfl[2][4];
#pragma unroll
      for (int p = 0; p < 2; p++) {
        const int brow = wC * 32 + p * 16 + l16;
        const uint32_t bo = st + 2 * MATB + (uint32_t)(brow * 128 + ((kc ^ (brow & 7)) << 4));
        ldm_x4(bfh[p], bo);
        ldm_x4(bfl[p], bo + MATB);
      }
#pragma unroll
      for (int p = 0; p < 2; p++) {
#pragma unroll
        for (int mt = 0; mt < 4; mt++) {
          // n-lower tile (nt = 2p): B frag = {r0, r2}; n-upper (nt = 2p+1): {r1, r3}
          mma16816(acc[mt][2 * p],     afh[mt], bfh[p][0], bfh[p][2]);
          mma16816(acc[mt][2 * p],     afh[mt], bfl[p][0], bfl[p][2]);
          mma16816(acc[mt][2 * p],     afl[mt], bfh[p][0], bfh[p][2]);
          mma16816(acc[mt][2 * p + 1], afh[mt], bfh[p][1], bfh[p][3]);
          mma16816(acc[mt][2 * p + 1], afh[mt], bfl[p][1], bfl[p][3]);
          mma16816(acc[mt][2 * p + 1], afl[mt], bfh[p][1], bfh[p][3]);
        }
      }
    }
    __syncthreads();
    const int nk = kt + NSTG;
    if (nk < KT) ld_stage(sb, slot, nk, tid, a_h, a_l, b_h, b_l, kbytes);
  }

  // epilogue
  const int gid = lane >> 2, tig = lane & 3;
#pragma unroll
  for (int mt = 0; mt < 4; mt++) {
    const int row = bm + wR * 64 + mt * 16 + gid;
#pragma unroll
    for (int nt = 0; nt < 4; nt++) {
      const int col = bn + wC * 32 + nt * 8 + tig * 2;
      if (col < Nn) {
        float2 v0 = make_float2(acc[mt][nt][0], acc[mt][nt][1]);
        float2 v1 = make_float2(acc[mt][nt][2], acc[mt][nt][3]);
        *reinterpret_cast<float2*>(C + (size_t)row * ldc + col) = v0;
        *reinterpret_cast<float2*>(C + (size_t)(row + 8) * ldc + col) = v1;
      }
    }
  }
}

// ======================= fp32 -> bf16 hi/lo split =======================
__global__ void __launch_bounds__(256) split_bf16_kernel(
    const float* __restrict__ src, int srcStride, int cols,
    __nv_bfloat16* __restrict__ hi, __nv_bfloat16* __restrict__ lo, int total) {
  int idx = blockIdx.x * 256 + threadIdx.x;
  if (idx >= total) return;
  int r = idx / cols, c = idx - r * cols;
  float x = src[(size_t)r * srcStride + c];
  __nv_bfloat16 h = __float2bfloat16_rn(x);
  float rem = x - __bfloat162float(h);
  hi[idx] = h;
  lo[idx] = __float2bfloat16_rn(rem);
}

// stacked small-weight matrix [Wfa;Wga;Wb;zeros] -> bf16 hi/lo [384, HID]
__global__ void __launch_bounds__(256) ws_build_kernel(
    const float* __restrict__ Wfa, const float* __restrict__ Wga,
    const float* __restrict__ Wb,
    __nv_bfloat16* __restrict__ hi, __nv_bfloat16* __restrict__ lo) {
  int idx = blockIdx.x * 256 + threadIdx.x;
  if (idx >= NS_PAD * HID) return;
  int r = idx / HID, c = idx - r * HID;
  float x = 0.f;
  if (r < 128) x = Wfa[r * HID + c];
  else if (r < 256) x = Wga[(r - 128) * HID + c];
  else if (r < NS_COMB) x = Wb[(r - 256) * HID + c];
  __nv_bfloat16 h = __float2bfloat16_rn(x);
  hi[idx] = h;
  lo[idx] = __float2bfloat16_rn(x - __bfloat162float(h));
}

// -------- depthwise causal conv(K=4) + SiLU, optional per-(n,h) L2 norm --------
__global__ void __launch_bounds__(128) conv_silu_kernel(
    const float* __restrict__ X, int xld, const float* __restrict__ W,
    float* __restrict__ Y, int do_norm, float scale) {
  const int h = blockIdx.x;
  const int n = blockIdx.y;
  const int tid = threadIdx.x;
  const int c = h * DK + tid;
  float y = 0.f;
#pragma unroll
  for (int i = 0; i < 4; i++) {
    int nn = n - 3 + i;
    if (nn >= 0) y = fmaf(X[(size_t)nn * xld + c], W[c * 4 + i], y);
  }
  y = y / (1.f + expf(-y));  // SiLU
  __shared__ float red[4];
  if (do_norm) {
    float ss = y * y;
#pragma unroll
    for (int o = 16; o > 0; o >>= 1) ss += __shfl_xor_sync(0xffffffffu, ss, o);
    if ((tid & 31) == 0) red[tid >> 5] = ss;
    __syncthreads();
    float tot = red[0] + red[1] + red[2] + red[3];
    y *= rsqrtf(tot + 1e-6f) * scale;
  }
  Y[(size_t)n * PROJ + c] = y;
}

// -------- exp(g) = exp(-exp(A_log[h]) * softplus(f + dt_bias)), in place --------
__global__ void __launch_bounds__(256) gate_decay_kernel(
    float* __restrict__ F, const float* __restrict__ dt_bias,
    const float* __restrict__ A_log) {
  const int idx = blockIdx.x * 256 + threadIdx.x;
  const int c = idx & (PROJ - 1);
  const int h = c >> 7;
  float x = F[idx] + dt_bias[c];
  float sp = (x > 20.f) ? x : log1pf(expf(x));
  F[idx] = expf(-expf(A_log[h]) * sp);
}

// ---------------- sequential delta-rule scan ----------------
__global__ void __launch_bounds__(256, 1) scan_kernel(
    const float* __restrict__ Q, const float* __restrict__ K,
    const float* __restrict__ V, const float* __restrict__ EG,
    const float* __restrict__ BRAW, int bstride, float* __restrict__ O) {
  const int h = blockIdx.x >> 2;
  const int vbase = (blockIdx.x & 3) << 5;
  const int tid = threadIdx.x;
  const int vloc = tid >> 3;
  const int kc = tid & 7;

  __shared__ float k_sh[2][128], q_sh[2][128], e_sh[2][128];
  __shared__ float v_sh[2][32];
  __shared__ float b_sh[2];

  float S[16];
#pragma unroll
  for (int j = 0; j < 16; j++) S[j] = 0.f;

  const size_t hb = (size_t)h * DK;
  float pk = 0.f, pe = 0.f, pq = 0.f, pv = 0.f, pb = 0.f;

  if (tid < 128) {
    pk = K[hb + tid];
    pe = EG[hb + tid];
  } else {
    int u = tid - 128;
    pq = Q[hb + u];
    if (u < 32) pv = V[hb + vbase + u];
    if (u == 127) pb = BRAW[h];
  }

  for (int t = 0; t < NSEQ; t++) {
    const int buf = t & 1;
    if (tid < 128) {
      int sw = ((tid & 15) << 3) | (tid >> 4);
      k_sh[buf][sw] = pk;
      e_sh[buf][sw] = pe;
    } else {
      int u = tid - 128;
      q_sh[buf][((u & 15) << 3) | (u >> 4)] = pq;
      if (u < 32) v_sh[buf][u] = pv;
      if (u == 127) b_sh[buf] = 1.f / (1.f + expf(-pb));
    }
    __syncthreads();

    if (t + 1 < NSEQ) {
      size_t off = (size_t)(t + 1) * PROJ + hb;
      if (tid < 128) {
        pk = K[off + tid];
        pe = EG[off + tid];
      } else {
        int u = tid - 128;
        pq = Q[off + u];
        if (u < 32) pv = V[off + vbase + u];
        if (u == 127) pb = BRAW[(size_t)(t + 1) * bstride + h];
      }
    }

    float kreg[16];
    float kv0 = 0.f, kv1 = 0.f;
#pragma unroll
    for (int j = 0; j < 16; j++) {
      float e = e_sh[buf][(j << 3) | kc];
      float kk = k_sh[buf][(j << 3) | kc];
      kreg[j] = kk;
      float s = S[j] * e;
      S[j] = s;
      if (j & 1) kv1 = fmaf(kk, s, kv1); else kv0 = fmaf(kk, s, kv0);
    }
    float kv = kv0 + kv1;
    kv += __shfl_xor_sync(0xffffffffu, kv, 1);
    kv += __shfl_xor_sync(0xffffffffu, kv, 2);
    kv += __shfl_xor_sync(0xffffffffu, kv, 4);

    const float delta = (v_sh[buf][vloc] - kv) * b_sh[buf];

    float o0 = 0.f, o1 = 0.f;
#pragma unroll
    for (int j = 0; j < 16; j++) {
      float q = q_sh[buf][(j << 3) | kc];
      float s = fmaf(kreg[j], delta, S[j]);
      S[j] = s;
      if (j & 1) o1 = fmaf(q, s, o1); else o0 = fmaf(q, s, o0);
    }
    float o = o0 + o1;
    o += __shfl_xor_sync(0xffffffffu, o, 1);
    o += __shfl_xor_sync(0xffffffffu, o, 2);
    o += __shfl_xor_sync(0xffffffffu, o, 4);
    if (kc == 0) O[(size_t)t * PROJ + hb + vbase + vloc] = o;
    __syncthreads();
  }
}

// -------- gated RMSNorm -> bf16 hi/lo directly --------
__global__ void __launch_bounds__(128) out_gate_kernel(
    const float* __restrict__ CORE, const float* __restrict__ GATE,
    const float* __restrict__ onorm_w,
    __nv_bfloat16* __restrict__ hi, __nv_bfloat16* __restrict__ lo) {
  const int h = blockIdx.x;
  const int n = blockIdx.y;
  const int tid = threadIdx.x;
  const size_t idx = (size_t)n * PROJ + h * DK + tid;
  float cv = CORE[idx];
  float ss = cv * cv;
#pragma unroll
  for (int o = 16; o > 0; o >>= 1) ss += __shfl_xor_sync(0xffffffffu, ss, o);
  __shared__ float red[4];
  if ((tid & 31) == 0) red[tid >> 5] = ss;
  __syncthreads();
  float tot = red[0] + red[1] + red[2] + red[3];
  float r = rsqrtf(tot * (1.f / 128.f) + 1e-5f);
  float gt = GATE[idx];
  float v = cv * r * onorm_w[tid] / (1.f + expf(-gt));
  __nv_bfloat16 hh = __float2bfloat16_rn(v);
  hi[idx] = hh;
  lo[idx] = __float2bfloat16_rn(v - __bfloat162float(hh));
}

// ---------------- launch ----------------
extern "C" void kernel_launch(void* const* d_in, const int* in_sizes, int n_in,
                              void* d_out, int out_size) {
  const float* hs      = (const float*)d_in[0];
  const float* Wq      = (const float*)d_in[1];
  const float* Wk      = (const float*)d_in[2];
  const float* Wv      = (const float*)d_in[3];
  const float* conv_q  = (const float*)d_in[4];
  const float* conv_k  = (const float*)d_in[5];
  const float* conv_v  = (const float*)d_in[6];
  const float* Wfa     = (const float*)d_in[7];
  const float* Wfb     = (const float*)d_in[8];
  const float* dt_bias = (const float*)d_in[9];
  const float* Wb      = (const float*)d_in[10];
  const float* A_log   = (const float*)d_in[11];
  const float* Wga     = (const float*)d_in[12];
  const float* Wgb     = (const float*)d_in[13];
  const float* onorm_w = (const float*)d_in[14];
  const float* Wo      = (const float*)d_in[15];
  float* out = (float*)d_out;

  float *QKVp, *Qc, *Kc, *Vc, *F, *GATE, *CORE, *COMB;
  __nv_bfloat16 *hsh, *hsl, *Wqkvh, *Wqkvl, *Woh, *Wol;
  __nv_bfloat16 *Wfbh, *Wfbl, *Wgbh, *Wgbl, *WSh, *WSl;
  __nv_bfloat16 *FAh, *FAl, *GAh, *GAl, *COREh, *COREl;
  cudaGetSymbolAddress((void**)&QKVp,  g_QKVp);
  cudaGetSymbolAddress((void**)&Qc,    g_Qc);
  cudaGetSymbolAddress((void**)&Kc,    g_Kc);
  cudaGetSymbolAddress((void**)&Vc,    g_Vc);
  cudaGetSymbolAddress((void**)&F,     g_F);
  cudaGetSymbolAddress((void**)&GATE,  g_GATE);
  cudaGetSymbolAddress((void**)&CORE,  g_CORE);
  cudaGetSymbolAddress((void**)&COMB,  g_COMB);
  cudaGetSymbolAddress((void**)&hsh,   g_hsh);
  cudaGetSymbolAddress((void**)&hsl,   g_hsl);
  cudaGetSymbolAddress((void**)&Wqkvh, g_Wqkvh);
  cudaGetSymbolAddress((void**)&Wqkvl, g_Wqkvl);
  cudaGetSymbolAddress((void**)&Woh,   g_Woh);
  cudaGetSymbolAddress((void**)&Wol,   g_Wol);
  cudaGetSymbolAddress((void**)&Wfbh,  g_Wfbh);
  cudaGetSymbolAddress((void**)&Wfbl,  g_Wfbl);
  cudaGetSymbolAddress((void**)&Wgbh,  g_Wgbh);
  cudaGetSymbolAddress((void**)&Wgbl,  g_Wgbl);
  cudaGetSymbolAddress((void**)&WSh,   g_WSh);
  cudaGetSymbolAddress((void**)&WSl,   g_WSl);
  cudaGetSymbolAddress((void**)&FAh,   g_FAh);
  cudaGetSymbolAddress((void**)&FAl,   g_FAl);
  cudaGetSymbolAddress((void**)&GAh,   g_GAh);
  cudaGetSymbolAddress((void**)&GAl,   g_GAl);
  cudaGetSymbolAddress((void**)&COREh, g_COREh);
  cudaGetSymbolAddress((void**)&COREl, g_COREl);

  cudaFuncSetAttribute(gemm_bf16s, cudaFuncAttributeMaxDynamicSharedMemorySize, SMEMB);

  // ---- split conversions ----
  int T;
  T = NSEQ * HID;
  split_bf16_kernel<<<(T + 255) / 256, 256>>>(hs, HID, HID, hsh, hsl, T);
  T = PROJ * HID;
  split_bf16_kernel<<<(T + 255) / 256, 256>>>(Wq, HID, HID, Wqkvh, Wqkvl, T);
  split_bf16_kernel<<<(T + 255) / 256, 256>>>(Wk, HID, HID, Wqkvh + (size_t)PROJ * HID,
                                              Wqkvl + (size_t)PROJ * HID, T);
  split_bf16_kernel<<<(T + 255) / 256, 256>>>(Wv, HID, HID, Wqkvh + (size_t)2 * PROJ * HID,
                                              Wqkvl + (size_t)2 * PROJ * HID, T);
  T = HID * PROJ;
  split_bf16_kernel<<<(T + 255) / 256, 256>>>(Wo, PROJ, PROJ, Woh, Wol, T);
  T = PROJ * DK;
  split_bf16_kernel<<<(T + 255) / 256, 256>>>(Wfb, DK, DK, Wfbh, Wfbl, T);
  split_bf16_kernel<<<(T + 255) / 256, 256>>>(Wgb, DK, DK, Wgbh, Wgbl, T);
  ws_build_kernel<<<(NS_PAD * HID + 255) / 256, 256>>>(Wfa, Wga, Wb, WSh, WSl);

  // ---- tensor-core GEMMs: fused QKV + fused small (FA|GA|beta) ----
  gemm_bf16s<<<dim3(QKVN / 128, NSEQ / 128), 256, SMEMB>>>(
      hsh, hsl, Wqkvh, Wqkvl, QKVp, QKVN, HID, QKVN);
  gemm_bf16s<<<dim3(3, NSEQ / 128), 256, SMEMB>>>(
      hsh, hsl, WSh, WSl, COMB, NS_COMB, HID, NS_COMB);

  // ---- conv + silu (+ l2 norm for q,k) ----
  dim3 gConv(NH, NSEQ);
  conv_silu_kernel<<<gConv, 128>>>(QKVp,            QKVN, conv_q, Qc, 1, QSCALE);
  conv_silu_kernel<<<gConv, 128>>>(QKVp + PROJ,     QKVN, conv_k, Kc, 1, 1.0f);
  conv_silu_kernel<<<gConv, 128>>>(QKVp + 2 * PROJ, QKVN, conv_v, Vc, 0, 1.0f);

  // ---- low-rank second projections (K=128, tensor core) ----
  T = NSEQ * DK;
  split_bf16_kernel<<<(T + 255) / 256, 256>>>(COMB, NS_COMB, DK, FAh, FAl, T);
  split_bf16_kernel<<<(T + 255) / 256, 256>>>(COMB + DK, NS_COMB, DK, GAh, GAl, T);
  gemm_bf16s<<<dim3(PROJ / 128, NSEQ / 128), 256, SMEMB>>>(
      FAh, FAl, Wfbh, Wfbl, F, PROJ, DK, PROJ);
  gemm_bf16s<<<dim3(PROJ / 128, NSEQ / 128), 256, SMEMB>>>(
      GAh, GAl, Wgbh, Wgbl, GATE, PROJ, DK, PROJ);

  // ---- decay gate ----
  gate_decay_kernel<<<(NSEQ * PROJ) / 256, 256>>>(F, dt_bias, A_log);

  // ---- recurrent scan ----
  scan_kernel<<<NH * 4, 256>>>(Qc, Kc, Vc, F, COMB + 256, NS_COMB, CORE);

  // ---- gated rmsnorm -> bf16 hi/lo directly ----
  out_gate_kernel<<<gConv, 128>>>(CORE, GATE, onorm_w, COREh, COREl);

  // ---- output projection ----
  gemm_bf16s<<<dim3(HID / 128, NSEQ / 128), 256, SMEMB>>>(
      COREh, COREl, Woh, Wol, out, HID, PROJ, HID);
}

// round 7
// speedup vs baseline: 2.0436x; 1.0067x over previous
#include <cuda_runtime.h>
#include <cuda_bf16.h>
#include <math.h>
#include <stdint.h>

#define NSEQ 2048
#define HID  2048
#define NH   32
#define DK   128
#define PROJ 4096
#define QKVN (3 * PROJ)
#define QSCALE 0.08838834764831843f     // 128^-0.5

#define NS_COMB   288                    // Wfa(128) + Wga(128) + Wb(32)
#define NS_PAD    384

// ---- GEMM tiling ----
#define BM 128
#define BN 128
#define BK 64
#define MATB   (128 * 128)               // one matrix tile: 128 rows x 128B = 16KB
#define STAGEB (4 * MATB)                // Ah,Al,Bh,Bl = 64KB
#define NSTG   3
#define SMEMB  (NSTG * STAGEB)           // 192KB

// ---------------- scratch (device globals; no allocation allowed) ----------------
__device__ __align__(256) float g_QKVp[NSEQ * QKVN];
__device__ __align__(256) float g_Qc[NSEQ * PROJ];
__device__ __align__(256) float g_Kc[NSEQ * PROJ];
__device__ __align__(256) float g_Vc[NSEQ * PROJ];
__device__ __align__(256) float g_F[NSEQ * PROJ];      // exp(g) written by GEMM epilogue
__device__ __align__(256) float g_GATE[NSEQ * PROJ];
__device__ __align__(256) float g_CORE[NSEQ * PROJ];
__device__ __align__(256) float g_COMB[NSEQ * NS_COMB];

__device__ __align__(256) __nv_bfloat16 g_hsh[NSEQ * HID];
__device__ __align__(256) __nv_bfloat16 g_hsl[NSEQ * HID];
__device__ __align__(256) __nv_bfloat16 g_Wqkvh[QKVN * HID];
__device__ __align__(256) __nv_bfloat16 g_Wqkvl[QKVN * HID];
__device__ __align__(256) __nv_bfloat16 g_Woh[HID * PROJ];
__device__ __align__(256) __nv_bfloat16 g_Wol[HID * PROJ];
__device__ __align__(256) __nv_bfloat16 g_Wfbh[PROJ * DK];
__device__ __align__(256) __nv_bfloat16 g_Wfbl[PROJ * DK];
__device__ __align__(256) __nv_bfloat16 g_Wgbh[PROJ * DK];
__device__ __align__(256) __nv_bfloat16 g_Wgbl[PROJ * DK];
__device__ __align__(256) __nv_bfloat16 g_WSh[NS_PAD * HID];
__device__ __align__(256) __nv_bfloat16 g_WSl[NS_PAD * HID];
__device__ __align__(256) __nv_bfloat16 g_FAh[NSEQ * DK];
__device__ __align__(256) __nv_bfloat16 g_FAl[NSEQ * DK];
__device__ __align__(256) __nv_bfloat16 g_GAh[NSEQ * DK];
__device__ __align__(256) __nv_bfloat16 g_GAl[NSEQ * DK];
__device__ __align__(256) __nv_bfloat16 g_COREh[NSEQ * PROJ];
__device__ __align__(256) __nv_bfloat16 g_COREl[NSEQ * PROJ];

// ============================ helpers (sm_80-portable PTX only) ============================
__device__ __forceinline__ uint32_t smem_u32(const void* p) {
  return (uint32_t)__cvta_generic_to_shared(p);
}
__device__ __forceinline__ void cp_async16(uint32_t dst, const void* src) {
  asm volatile("cp.async.cg.shared.global [%0], [%1], 16;" :: "r"(dst), "l"(src) : "memory");
}
__device__ __forceinline__ void cp_commit() {
  asm volatile("cp.async.commit_group;" ::: "memory");
}
template<int N> __device__ __forceinline__ void cp_wait() {
  asm volatile("cp.async.wait_group %0;" :: "n"(N) : "memory");
}
__device__ __forceinline__ void ldm_x4(uint32_t* r, uint32_t addr) {
  asm volatile("ldmatrix.sync.aligned.m8n8.x4.shared.b16 {%0,%1,%2,%3}, [%4];"
               : "=r"(r[0]), "=r"(r[1]), "=r"(r[2]), "=r"(r[3]) : "r"(addr));
}
__device__ __forceinline__ void mma16816(float* c, const uint32_t* a,
                                         uint32_t b0, uint32_t b1) {
  asm volatile(
      "mma.sync.aligned.m16n8k16.row.col.f32.bf16.bf16.f32 "
      "{%0,%1,%2,%3}, {%4,%5,%6,%7}, {%8,%9}, {%0,%1,%2,%3};"
      : "+f"(c[0]), "+f"(c[1]), "+f"(c[2]), "+f"(c[3])
      : "r"(a[0]), "r"(a[1]), "r"(a[2]), "r"(a[3]), "r"(b0), "r"(b1));
}
__device__ __forceinline__ uint16_t bf16_bits(__nv_bfloat16 h) {
  return *reinterpret_cast<uint16_t*>(&h);
}

// ======================= bf16 hi/lo split GEMM (mma.sync + ldmatrix) =======================
// C[M,Nn] = A[M,K] * B[Nn,K]^T ; 3 passes Ah*Bh + Ah*Bl + Al*Bh.
// EPI: 0 = plain fp32 store, 1 = decay-gate epilogue (exp(-exp(A_log)*softplus(x+dt_bias))).
__device__ __forceinline__ void ld_stage(uint32_t sb, int slot, int kt, int tid,
                                         const char* a_h, const char* a_l,
                                         const char* b_h, const char* b_l,
                                         size_t kbytes) {
  const uint32_t st = sb + (uint32_t)slot * STAGEB;
#pragma unroll
  for (int i = 0; i < 4; i++) {
    const int chunk = i * 256 + tid;          // 0..1023
    const int row = chunk >> 3, kc = chunk & 7;
    const uint32_t so = (uint32_t)(row * 128 + ((kc ^ (row & 7)) << 4));
    const size_t go = (size_t)row * kbytes + (size_t)kt * 128 + (size_t)(kc << 4);
    cp_async16(st + so,            a_h + go);
    cp_async16(st + MATB + so,     a_l + go);
    cp_async16(st + 2 * MATB + so, b_h + go);
    cp_async16(st + 3 * MATB + so, b_l + go);
  }
  cp_commit();
}

template <int EPI>
__global__ void __launch_bounds__(256, 1) gemm_bf16s(
    const __nv_bfloat16* __restrict__ Ah, const __nv_bfloat16* __restrict__ Al,
    const __nv_bfloat16* __restrict__ Bh, const __nv_bfloat16* __restrict__ Bl,
    float* __restrict__ C, int Nn, int K, int ldc,
    const float* __restrict__ dt_bias, const float* __restrict__ A_log) {
  extern __shared__ char sm[];
  const int tid = threadIdx.x;
  const int bm = blockIdx.y * BM, bn = blockIdx.x * BN;
  const uint32_t sb = smem_u32(sm);

  const int lane = tid & 31, warp = tid >> 5;
  const int l16 = lane & 15, lh = lane >> 4;
  const int wR = warp >> 2;            // 0..1  (M, 64 rows)
  const int wC = warp & 3;             // 0..3  (N, 32 cols)

  const size_t kbytes = (size_t)K * 2;
  const char* a_h = (const char*)Ah + (size_t)bm * kbytes;
  const char* a_l = (const char*)Al + (size_t)bm * kbytes;
  const char* b_h = (const char*)Bh + (size_t)bn * kbytes;
  const char* b_l = (const char*)Bl + (size_t)bn * kbytes;

  float acc[4][4][4];
#pragma unroll
  for (int i = 0; i < 4; i++)
#pragma unroll
    for (int j = 0; j < 4; j++)
#pragma unroll
      for (int r = 0; r < 4; r++) acc[i][j][r] = 0.f;

  const int KT = K / BK;
  // prologue: NSTG-1 stages in flight
  for (int s = 0; s < NSTG - 1 && s < KT; s++)
    ld_stage(sb, s, s, tid, a_h, a_l, b_h, b_l, kbytes);

#pragma unroll 1
  for (int kt = 0; kt < KT; kt++) {
    const int slot = kt % NSTG;
    int pend = KT - 1 - kt; if (pend > NSTG - 2) pend = NSTG - 2;
    if (pend >= 1) cp_wait<1>(); else cp_wait<0>();
    __syncthreads();                       // single barrier per K-tile

    const int nk = kt + NSTG - 1;
    if (nk < KT) ld_stage(sb, nk % NSTG, nk, tid, a_h, a_l, b_h, b_l, kbytes);

    const uint32_t st = sb + (uint32_t)slot * STAGEB;
#pragma unroll
    for (int kk = 0; kk < 4; kk++) {
      const int kc = kk * 2 + lh;       // 16B chunk index within 128B row
      uint32_t afh[4][4], afl[4][4];
#pragma unroll
      for (int mt = 0; mt < 4; mt++) {
        const int arow = wR * 64 + mt * 16 + l16;
        const uint32_t ao = st + (uint32_t)(arow * 128 + ((kc ^ (arow & 7)) << 4));
        ldm_x4(afh[mt], ao);
        ldm_x4(afl[mt], ao + MATB);
      }
      uint32_t bfh[2][4], bfl[2][4];
#pragma unroll
      for (int p = 0; p < 2; p++) {
        const int brow = wC * 32 + p * 16 + l16;
        const uint32_t bo = st + 2 * MATB + (uint32_t)(brow * 128 + ((kc ^ (brow & 7)) << 4));
        ldm_x4(bfh[p], bo);
        ldm_x4(bfl[p], bo + MATB);
      }
#pragma unroll
      for (int p = 0; p < 2; p++) {
#pragma unroll
        for (int mt = 0; mt < 4; mt++) {
          mma16816(acc[mt][2 * p],     afh[mt], bfh[p][0], bfh[p][2]);
          mma16816(acc[mt][2 * p],     afh[mt], bfl[p][0], bfl[p][2]);
          mma16816(acc[mt][2 * p],     afl[mt], bfh[p][0], bfh[p][2]);
          mma16816(acc[mt][2 * p + 1], afh[mt], bfh[p][1], bfh[p][3]);
          mma16816(acc[mt][2 * p + 1], afh[mt], bfl[p][1], bfl[p][3]);
          mma16816(acc[mt][2 * p + 1], afl[mt], bfh[p][1], bfh[p][3]);
        }
      }
    }
  }

  // epilogue
  const int gid = lane >> 2, tig = lane & 3;
#pragma unroll
  for (int mt = 0; mt < 4; mt++) {
    const int row = bm + wR * 64 + mt * 16 + gid;
#pragma unroll
    for (int nt = 0; nt < 4; nt++) {
      const int col = bn + wC * 32 + nt * 8 + tig * 2;
      if (col < Nn) {
        float v[4] = {acc[mt][nt][0], acc[mt][nt][1], acc[mt][nt][2], acc[mt][nt][3]};
        if (EPI == 1) {
          const float d0 = dt_bias[col], d1 = dt_bias[col + 1];
          const float na = -expf(A_log[col >> 7]);
#pragma unroll
          for (int r = 0; r < 4; r++) {
            float x = v[r] + ((r & 1) ? d1 : d0);
            float sp = (x > 20.f) ? x : log1pf(expf(x));
            v[r] = expf(na * sp);
          }
        }
        *reinterpret_cast<float2*>(C + (size_t)row * ldc + col) = make_float2(v[0], v[1]);
        *reinterpret_cast<float2*>(C + (size_t)(row + 8) * ldc + col) = make_float2(v[2], v[3]);
      }
    }
  }
}

// ======================= fp32 -> bf16 hi/lo split (vectorized x4) =======================
__global__ void __launch_bounds__(256) split_bf16_kernel(
    const float* __restrict__ src, int srcStride, int cols,
    __nv_bfloat16* __restrict__ hi, __nv_bfloat16* __restrict__ lo, int total4) {
  int i = blockIdx.x * 256 + threadIdx.x;
  if (i >= total4) return;
  const int idx = i * 4;
  const int r = idx / cols, c = idx - r * cols;   // cols multiple of 4, row-aligned
  const float4 x = *reinterpret_cast<const float4*>(src + (size_t)r * srcStride + c);
  __nv_bfloat16 h0 = __float2bfloat16_rn(x.x), h1 = __float2bfloat16_rn(x.y);
  __nv_bfloat16 h2 = __float2bfloat16_rn(x.z), h3 = __float2bfloat16_rn(x.w);
  __nv_bfloat16 l0 = __float2bfloat16_rn(x.x - __bfloat162float(h0));
  __nv_bfloat16 l1 = __float2bfloat16_rn(x.y - __bfloat162float(h1));
  __nv_bfloat16 l2 = __float2bfloat16_rn(x.z - __bfloat162float(h2));
  __nv_bfloat16 l3 = __float2bfloat16_rn(x.w - __bfloat162float(h3));
  uint2 hw, lw;
  hw.x = (uint32_t)bf16_bits(h0) | ((uint32_t)bf16_bits(h1) << 16);
  hw.y = (uint32_t)bf16_bits(h2) | ((uint32_t)bf16_bits(h3) << 16);
  lw.x = (uint32_t)bf16_bits(l0) | ((uint32_t)bf16_bits(l1) << 16);
  lw.y = (uint32_t)bf16_bits(l2) | ((uint32_t)bf16_bits(l3) << 16);
  *reinterpret_cast<uint2*>(hi + idx) = hw;
  *reinterpret_cast<uint2*>(lo + idx) = lw;
}

// stacked small-weight matrix [Wfa;Wga;Wb;zeros] -> bf16 hi/lo [384, HID]
__global__ void __launch_bounds__(256) ws_build_kernel(
    const float* __restrict__ Wfa, const float* __restrict__ Wga,
    const float* __restrict__ Wb,
    __nv_bfloat16* __restrict__ hi, __nv_bfloat16* __restrict__ lo) {
  int idx = blockIdx.x * 256 + threadIdx.x;
  if (idx >= NS_PAD * HID) return;
  int r = idx / HID, c = idx - r * HID;
  float x = 0.f;
  if (r < 128) x = Wfa[r * HID + c];
  else if (r < 256) x = Wga[(r - 128) * HID + c];
  else if (r < NS_COMB) x = Wb[(r - 256) * HID + c];
  __nv_bfloat16 h = __float2bfloat16_rn(x);
  hi[idx] = h;
  lo[idx] = __float2bfloat16_rn(x - __bfloat162float(h));
}

// -------- depthwise causal conv(K=4) + SiLU, optional per-(n,h) L2 norm --------
__global__ void __launch_bounds__(128) conv_silu_kernel(
    const float* __restrict__ X, int xld, const float* __restrict__ W,
    float* __restrict__ Y, int do_norm, float scale) {
  const int h = blockIdx.x;
  const int n = blockIdx.y;
  const int tid = threadIdx.x;
  const int c = h * DK + tid;
  float y = 0.f;
#pragma unroll
  for (int i = 0; i < 4; i++) {
    int nn = n - 3 + i;
    if (nn >= 0) y = fmaf(X[(size_t)nn * xld + c], W[c * 4 + i], y);
  }
  y = y / (1.f + expf(-y));  // SiLU
  __shared__ float red[4];
  if (do_norm) {
    float ss = y * y;
#pragma unroll
    for (int o = 16; o > 0; o >>= 1) ss += __shfl_xor_sync(0xffffffffu, ss, o);
    if ((tid & 31) == 0) red[tid >> 5] = ss;
    __syncthreads();
    float tot = red[0] + red[1] + red[2] + red[3];
    y *= rsqrtf(tot + 1e-6f) * scale;
  }
  Y[(size_t)n * PROJ + c] = y;
}

// ---------------- sequential delta-rule scan ----------------
__global__ void __launch_bounds__(256, 1) scan_kernel(
    const float* __restrict__ Q, const float* __restrict__ K,
    const float* __restrict__ V, const float* __restrict__ EG,
    const float* __restrict__ BRAW, int bstride, float* __restrict__ O) {
  const int h = blockIdx.x >> 2;
  const int vbase = (blockIdx.x & 3) << 5;
  const int tid = threadIdx.x;
  const int vloc = tid >> 3;
  const int kc = tid & 7;

  __shared__ float k_sh[2][128], q_sh[2][128], e_sh[2][128];
  __shared__ float v_sh[2][32];
  __shared__ float b_sh[2];

  float S[16];
#pragma unroll
  for (int j = 0; j < 16; j++) S[j] = 0.f;

  const size_t hb = (size_t)h * DK;
  float pk = 0.f, pe = 0.f, pq = 0.f, pv = 0.f, pb = 0.f;

  if (tid < 128) {
    pk = K[hb + tid];
    pe = EG[hb + tid];
  } else {
    int u = tid - 128;
    pq = Q[hb + u];
    if (u < 32) pv = V[hb + vbase + u];
    if (u == 127) pb = BRAW[h];
  }

  for (int t = 0; t < NSEQ; t++) {
    const int buf = t & 1;
    if (tid < 128) {
      int sw = ((tid & 15) << 3) | (tid >> 4);
      k_sh[buf][sw] = pk;
      e_sh[buf][sw] = pe;
    } else {
      int u = tid - 128;
      q_sh[buf][((u & 15) << 3) | (u >> 4)] = pq;
      if (u < 32) v_sh[buf][u] = pv;
      if (u == 127) b_sh[buf] = 1.f / (1.f + expf(-pb));
    }
    __syncthreads();

    if (t + 1 < NSEQ) {
      size_t off = (size_t)(t + 1) * PROJ + hb;
      if (tid < 128) {
        pk = K[off + tid];
        pe = EG[off + tid];
      } else {
        int u = tid - 128;
        pq = Q[off + u];
        if (u < 32) pv = V[off + vbase + u];
        if (u == 127) pb = BRAW[(size_t)(t + 1) * bstride + h];
      }
    }

    float kreg[16];
    float kv0 = 0.f, kv1 = 0.f;
#pragma unroll
    for (int j = 0; j < 16; j++) {
      float e = e_sh[buf][(j << 3) | kc];
      float kk = k_sh[buf][(j << 3) | kc];
      kreg[j] = kk;
      float s = S[j] * e;
      S[j] = s;
      if (j & 1) kv1 = fmaf(kk, s, kv1); else kv0 = fmaf(kk, s, kv0);
    }
    float kv = kv0 + kv1;
    kv += __shfl_xor_sync(0xffffffffu, kv, 1);
    kv += __shfl_xor_sync(0xffffffffu, kv, 2);
    kv += __shfl_xor_sync(0xffffffffu, kv, 4);

    const float delta = (v_sh[buf][vloc] - kv) * b_sh[buf];

    float o0 = 0.f, o1 = 0.f;
#pragma unroll
    for (int j = 0; j < 16; j++) {
      float q = q_sh[buf][(j << 3) | kc];
      float s = fmaf(kreg[j], delta, S[j]);
      S[j] = s;
      if (j & 1) o1 = fmaf(q, s, o1); else o0 = fmaf(q, s, o0);
    }
    float o = o0 + o1;
    o += __shfl_xor_sync(0xffffffffu, o, 1);
    o += __shfl_xor_sync(0xffffffffu, o, 2);
    o += __shfl_xor_sync(0xffffffffu, o, 4);
    if (kc == 0) O[(size_t)t * PROJ + hb + vbase + vloc] = o;
    __syncthreads();
  }
}

// -------- gated RMSNorm -> bf16 hi/lo directly (paired 4B stores) --------
__global__ void __launch_bounds__(128) out_gate_kernel(
    const float* __restrict__ CORE, const float* __restrict__ GATE,
    const float* __restrict__ onorm_w,
    __nv_bfloat16* __restrict__ hi, __nv_bfloat16* __restrict__ lo) {
  const int h = blockIdx.x;
  const int n = blockIdx.y;
  const int tid = threadIdx.x;
  const size_t idx = (size_t)n * PROJ + h * DK + tid;
  float cv = CORE[idx];
  float ss = cv * cv;
#pragma unroll
  for (int o = 16; o > 0; o >>= 1) ss += __shfl_xor_sync(0xffffffffu, ss, o);
  __shared__ float red[4];
  if ((tid & 31) == 0) red[tid >> 5] = ss;
  __syncthreads();
  float tot = red[0] + red[1] + red[2] + red[3];
  float r = rsqrtf(tot * (1.f / 128.f) + 1e-5f);
  float gt = GATE[idx];
  float v = cv * r * onorm_w[tid] / (1.f + expf(-gt));
  __nv_bfloat16 hh = __float2bfloat16_rn(v);
  __nv_bfloat16 ll = __float2bfloat16_rn(v - __bfloat162float(hh));
  uint32_t hw = bf16_bits(hh), lw = bf16_bits(ll);
  uint32_t hn = __shfl_down_sync(0xffffffffu, hw, 1);
  uint32_t ln = __shfl_down_sync(0xffffffffu, lw, 1);
  if ((tid & 1) == 0) {
    *reinterpret_cast<uint32_t*>(hi + idx) = hw | (hn << 16);
    *reinterpret_cast<uint32_t*>(lo + idx) = lw | (ln << 16);
  }
}

// ---------------- launch ----------------
extern "C" void kernel_launch(void* const* d_in, const int* in_sizes, int n_in,
                              void* d_out, int out_size) {
  const float* hs      = (const float*)d_in[0];
  const float* Wq      = (const float*)d_in[1];
  const float* Wk      = (const float*)d_in[2];
  const float* Wv      = (const float*)d_in[3];
  const float* conv_q  = (const float*)d_in[4];
  const float* conv_k  = (const float*)d_in[5];
  const float* conv_v  = (const float*)d_in[6];
  const float* Wfa     = (const float*)d_in[7];
  const float* Wfb     = (const float*)d_in[8];
  const float* dt_bias = (const float*)d_in[9];
  const float* Wb      = (const float*)d_in[10];
  const float* A_log   = (const float*)d_in[11];
  const float* Wga     = (const float*)d_in[12];
  const float* Wgb     = (const float*)d_in[13];
  const float* onorm_w = (const float*)d_in[14];
  const float* Wo      = (const float*)d_in[15];
  float* out = (float*)d_out;

  float *QKVp, *Qc, *Kc, *Vc, *F, *GATE, *CORE, *COMB;
  __nv_bfloat16 *hsh, *hsl, *Wqkvh, *Wqkvl, *Woh, *Wol;
  __nv_bfloat16 *Wfbh, *Wfbl, *Wgbh, *Wgbl, *WSh, *WSl;
  __nv_bfloat16 *FAh, *FAl, *GAh, *GAl, *COREh, *COREl;
  cudaGetSymbolAddress((void**)&QKVp,  g_QKVp);
  cudaGetSymbolAddress((void**)&Qc,    g_Qc);
  cudaGetSymbolAddress((void**)&Kc,    g_Kc);
  cudaGetSymbolAddress((void**)&Vc,    g_Vc);
  cudaGetSymbolAddress((void**)&F,     g_F);
  cudaGetSymbolAddress((void**)&GATE,  g_GATE);
  cudaGetSymbolAddress((void**)&CORE,  g_CORE);
  cudaGetSymbolAddress((void**)&COMB,  g_COMB);
  cudaGetSymbolAddress((void**)&hsh,   g_hsh);
  cudaGetSymbolAddress((void**)&hsl,   g_hsl);
  cudaGetSymbolAddress((void**)&Wqkvh, g_Wqkvh);
  cudaGetSymbolAddress((void**)&Wqkvl, g_Wqkvl);
  cudaGetSymbolAddress((void**)&Woh,   g_Woh);
  cudaGetSymbolAddress((void**)&Wol,   g_Wol);
  cudaGetSymbolAddress((void**)&Wfbh,  g_Wfbh);
  cudaGetSymbolAddress((void**)&Wfbl,  g_Wfbl);
  cudaGetSymbolAddress((void**)&Wgbh,  g_Wgbh);
  cudaGetSymbolAddress((void**)&Wgbl,  g_Wgbl);
  cudaGetSymbolAddress((void**)&WSh,   g_WSh);
  cudaGetSymbolAddress((void**)&WSl,   g_WSl);
  cudaGetSymbolAddress((void**)&FAh,   g_FAh);
  cudaGetSymbolAddress((void**)&FAl,   g_FAl);
  cudaGetSymbolAddress((void**)&GAh,   g_GAh);
  cudaGetSymbolAddress((void**)&GAl,   g_GAl);
  cudaGetSymbolAddress((void**)&COREh, g_COREh);
  cudaGetSymbolAddress((void**)&COREl, g_COREl);

  cudaFuncSetAttribute(gemm_bf16s<0>, cudaFuncAttributeMaxDynamicSharedMemorySize, SMEMB);
  cudaFuncSetAttribute(gemm_bf16s<1>, cudaFuncAttributeMaxDynamicSharedMemorySize, SMEMB);

  // ---- split conversions (vectorized x4) ----
  int T4;
  T4 = NSEQ * HID / 4;
  split_bf16_kernel<<<(T4 + 255) / 256, 256>>>(hs, HID, HID, hsh, hsl, T4);
  T4 = PROJ * HID / 4;
  split_bf16_kernel<<<(T4 + 255) / 256, 256>>>(Wq, HID, HID, Wqkvh, Wqkvl, T4);
  split_bf16_kernel<<<(T4 + 255) / 256, 256>>>(Wk, HID, HID, Wqkvh + (size_t)PROJ * HID,
                                               Wqkvl + (size_t)PROJ * HID, T4);
  split_bf16_kernel<<<(T4 + 255) / 256, 256>>>(Wv, HID, HID, Wqkvh + (size_t)2 * PROJ * HID,
                                               Wqkvl + (size_t)2 * PROJ * HID, T4);
  T4 = HID * PROJ / 4;
  split_bf16_kernel<<<(T4 + 255) / 256, 256>>>(Wo, PROJ, PROJ, Woh, Wol, T4);
  T4 = PROJ * DK / 4;
  split_bf16_kernel<<<(T4 + 255) / 256, 256>>>(Wfb, DK, DK, Wfbh, Wfbl, T4);
  split_bf16_kernel<<<(T4 + 255) / 256, 256>>>(Wgb, DK, DK, Wgbh, Wgbl, T4);
  ws_build_kernel<<<(NS_PAD * HID + 255) / 256, 256>>>(Wfa, Wga, Wb, WSh, WSl);

  // ---- tensor-core GEMMs: fused QKV + fused small (FA|GA|beta) ----
  gemm_bf16s<0><<<dim3(QKVN / 128, NSEQ / 128), 256, SMEMB>>>(
      hsh, hsl, Wqkvh, Wqkvl, QKVp, QKVN, HID, QKVN, nullptr, nullptr);
  gemm_bf16s<0><<<dim3(3, NSEQ / 128), 256, SMEMB>>>(
      hsh, hsl, WSh, WSl, COMB, NS_COMB, HID, NS_COMB, nullptr, nullptr);

  // ---- conv + silu (+ l2 norm for q,k) ----
  dim3 gConv(NH, NSEQ);
  conv_silu_kernel<<<gConv, 128>>>(QKVp,            QKVN, conv_q, Qc, 1, QSCALE);
  conv_silu_kernel<<<gConv, 128>>>(QKVp + PROJ,     QKVN, conv_k, Kc, 1, 1.0f);
  conv_silu_kernel<<<gConv, 128>>>(QKVp + 2 * PROJ, QKVN, conv_v, Vc, 0, 1.0f);

  // ---- low-rank second projections (K=128), F with fused decay epilogue ----
  T4 = NSEQ * DK / 4;
  split_bf16_kernel<<<(T4 + 255) / 256, 256>>>(COMB, NS_COMB, DK, FAh, FAl, T4);
  split_bf16_kernel<<<(T4 + 255) / 256, 256>>>(COMB + DK, NS_COMB, DK, GAh, GAl, T4);
  gemm_bf16s<1><<<dim3(PROJ / 128, NSEQ / 128), 256, SMEMB>>>(
      FAh, FAl, Wfbh, Wfbl, F, PROJ, DK, PROJ, dt_bias, A_log);
  gemm_bf16s<0><<<dim3(PROJ / 128, NSEQ / 128), 256, SMEMB>>>(
      GAh, GAl, Wgbh, Wgbl, GATE, PROJ, DK, PROJ, nullptr, nullptr);

  // ---- recurrent scan ----
  scan_kernel<<<NH * 4, 256>>>(Qc, Kc, Vc, F, COMB + 256, NS_COMB, CORE);

  // ---- gated rmsnorm -> bf16 hi/lo directly ----
  out_gate_kernel<<<gConv, 128>>>(CORE, GATE, onorm_w, COREh, COREl);

  // ---- output projection ----
  gemm_bf16s<0><<<dim3(HID / 128, NSEQ / 128), 256, SMEMB>>>(
      COREh, COREl, Woh, Wol, out, HID, PROJ, HID, nullptr, nullptr);
}

// round 8
// speedup vs baseline: 2.0742x; 1.0149x over previous
#include <cuda_runtime.h>
#include <cuda_bf16.h>
#include <math.h>
#include <stdint.h>

#define NSEQ 2048
#define HID  2048
#define NH   32
#define DK   128
#define PROJ 4096
#define QKVN (3 * PROJ)
#define QSCALE 0.08838834764831843f     // 128^-0.5

#define NS_COMB   288                    // Wfa(128) + Wga(128) + Wb(32)
#define NS_PAD    384

// ---- GEMM tiling ----
#define BM 128
#define BN 128
#define BK 32
#define MATB   (128 * 64)                // one matrix tile: 128 rows x 64B = 8KB
#define STAGEB (4 * MATB)                // Ah,Al,Bh,Bl = 32KB
#define NSTG   3
#define SMEMB  (NSTG * STAGEB)           // 96KB -> 2 CTAs/SM

// ---------------- scratch (device globals; no allocation allowed) ----------------
__device__ __align__(256) float g_QKVp[NSEQ * QKVN];
__device__ __align__(256) float g_Qc[NSEQ * PROJ];
__device__ __align__(256) float g_Kc[NSEQ * PROJ];
__device__ __align__(256) float g_Vc[NSEQ * PROJ];
__device__ __align__(256) float g_F[NSEQ * PROJ];      // exp(g) written by GEMM epilogue
__device__ __align__(256) float g_GATE[NSEQ * PROJ];
__device__ __align__(256) float g_CORE[NSEQ * PROJ];
__device__ __align__(256) float g_COMB[NSEQ * NS_COMB];

__device__ __align__(256) __nv_bfloat16 g_hsh[NSEQ * HID];
__device__ __align__(256) __nv_bfloat16 g_hsl[NSEQ * HID];
__device__ __align__(256) __nv_bfloat16 g_Wqkvh[QKVN * HID];
__device__ __align__(256) __nv_bfloat16 g_Wqkvl[QKVN * HID];
__device__ __align__(256) __nv_bfloat16 g_Woh[HID * PROJ];
__device__ __align__(256) __nv_bfloat16 g_Wol[HID * PROJ];
__device__ __align__(256) __nv_bfloat16 g_Wfbh[PROJ * DK];
__device__ __align__(256) __nv_bfloat16 g_Wfbl[PROJ * DK];
__device__ __align__(256) __nv_bfloat16 g_Wgbh[PROJ * DK];
__device__ __align__(256) __nv_bfloat16 g_Wgbl[PROJ * DK];
__device__ __align__(256) __nv_bfloat16 g_WSh[NS_PAD * HID];
__device__ __align__(256) __nv_bfloat16 g_WSl[NS_PAD * HID];
__device__ __align__(256) __nv_bfloat16 g_FAh[NSEQ * DK];
__device__ __align__(256) __nv_bfloat16 g_FAl[NSEQ * DK];
__device__ __align__(256) __nv_bfloat16 g_GAh[NSEQ * DK];
__device__ __align__(256) __nv_bfloat16 g_GAl[NSEQ * DK];
__device__ __align__(256) __nv_bfloat16 g_COREh[NSEQ * PROJ];
__device__ __align__(256) __nv_bfloat16 g_COREl[NSEQ * PROJ];

// ============================ helpers (sm_80-portable PTX only) ============================
__device__ __forceinline__ uint32_t smem_u32(const void* p) {
  return (uint32_t)__cvta_generic_to_shared(p);
}
__device__ __forceinline__ void cp_async16(uint32_t dst, const void* src) {
  asm volatile("cp.async.cg.shared.global [%0], [%1], 16;" :: "r"(dst), "l"(src) : "memory");
}
__device__ __forceinline__ void cp_commit() {
  asm volatile("cp.async.commit_group;" ::: "memory");
}
template<int N> __device__ __forceinline__ void cp_wait() {
  asm volatile("cp.async.wait_group %0;" :: "n"(N) : "memory");
}
__device__ __forceinline__ void ldm_x4(uint32_t* r, uint32_t addr) {
  asm volatile("ldmatrix.sync.aligned.m8n8.x4.shared.b16 {%0,%1,%2,%3}, [%4];"
               : "=r"(r[0]), "=r"(r[1]), "=r"(r[2]), "=r"(r[3]) : "r"(addr));
}
__device__ __forceinline__ void mma16816(float* c, const uint32_t* a,
                                         uint32_t b0, uint32_t b1) {
  asm volatile(
      "mma.sync.aligned.m16n8k16.row.col.f32.bf16.bf16.f32 "
      "{%0,%1,%2,%3}, {%4,%5,%6,%7}, {%8,%9}, {%0,%1,%2,%3};"
      : "+f"(c[0]), "+f"(c[1]), "+f"(c[2]), "+f"(c[3])
      : "r"(a[0]), "r"(a[1]), "r"(a[2]), "r"(a[3]), "r"(b0), "r"(b1));
}
__device__ __forceinline__ uint16_t bf16_bits(__nv_bfloat16 h) {
  return *reinterpret_cast<uint16_t*>(&h);
}
// 64B-row swizzle: chunk' = kc ^ ((row>>1)&3); conflict-free for cp.async stores
// (8-lane 128B spans hit 8 distinct 16B groups) and ldmatrix 8-row phases.
__device__ __forceinline__ uint32_t sw64(int row, int kc) {
  return (uint32_t)(row * 64 + ((kc ^ ((row >> 1) & 3)) << 4));
}

// ======================= bf16 hi/lo split GEMM (mma.sync + ldmatrix) =======================
// C[M,Nn] = A[M,K] * B[Nn,K]^T ; 3 passes Ah*Bh + Ah*Bl + Al*Bh.
// EPI: 0 = plain fp32 store, 1 = decay-gate epilogue.
__device__ __forceinline__ void ld_stage(uint32_t sb, int slot, int kt, int tid,
                                         const char* a_h, const char* a_l,
                                         const char* b_h, const char* b_l,
                                         size_t kbytes) {
  const uint32_t st = sb + (uint32_t)slot * STAGEB;
#pragma unroll
  for (int i = 0; i < 2; i++) {
    const int chunk = i * 256 + tid;          // 0..511 (128 rows x 4 chunks)
    const int row = chunk >> 2, kc = chunk & 3;
    const uint32_t so = sw64(row, kc);
    const size_t go = (size_t)row * kbytes + (size_t)kt * 64 + (size_t)(kc << 4);
    cp_async16(st + so,            a_h + go);
    cp_async16(st + MATB + so,     a_l + go);
    cp_async16(st + 2 * MATB + so, b_h + go);
    cp_async16(st + 3 * MATB + so, b_l + go);
  }
  cp_commit();
}

template <int EPI>
__global__ void __launch_bounds__(256, 2) gemm_bf16s(
    const __nv_bfloat16* __restrict__ Ah, const __nv_bfloat16* __restrict__ Al,
    const __nv_bfloat16* __restrict__ Bh, const __nv_bfloat16* __restrict__ Bl,
    float* __restrict__ C, int Nn, int K, int ldc,
    const float* __restrict__ dt_bias, const float* __restrict__ A_log) {
  extern __shared__ char sm[];
  const int tid = threadIdx.x;
  const int bm = blockIdx.y * BM, bn = blockIdx.x * BN;
  const uint32_t sb = smem_u32(sm);

  const int lane = tid & 31, warp = tid >> 5;
  const int l16 = lane & 15, lh = lane >> 4;
  const int wR = warp >> 2;            // 0..1  (M, 64 rows)
  const int wC = warp & 3;             // 0..3  (N, 32 cols)

  const size_t kbytes = (size_t)K * 2;
  const char* a_h = (const char*)Ah + (size_t)bm * kbytes;
  const char* a_l = (const char*)Al + (size_t)bm * kbytes;
  const char* b_h = (const char*)Bh + (size_t)bn * kbytes;
  const char* b_l = (const char*)Bl + (size_t)bn * kbytes;

  float acc[4][4][4];
#pragma unroll
  for (int i = 0; i < 4; i++)
#pragma unroll
    for (int j = 0; j < 4; j++)
#pragma unroll
      for (int r = 0; r < 4; r++) acc[i][j][r] = 0.f;

  const int KT = K / BK;
  for (int s = 0; s < NSTG - 1 && s < KT; s++)
    ld_stage(sb, s, s, tid, a_h, a_l, b_h, b_l, kbytes);

#pragma unroll 1
  for (int kt = 0; kt < KT; kt++) {
    const int slot = kt % NSTG;
    int pend = KT - 1 - kt; if (pend > NSTG - 2) pend = NSTG - 2;
    if (pend >= 1) cp_wait<1>(); else cp_wait<0>();
    __syncthreads();

    const int nk = kt + NSTG - 1;
    if (nk < KT) ld_stage(sb, nk % NSTG, nk, tid, a_h, a_l, b_h, b_l, kbytes);

    const uint32_t st = sb + (uint32_t)slot * STAGEB;
#pragma unroll
    for (int kk = 0; kk < 2; kk++) {
      const int kc = kk * 2 + lh;       // 16B chunk index within 64B row
      uint32_t afh[4][4], afl[4][4];
#pragma unroll
      for (int mt = 0; mt < 4; mt++) {
        const int arow = wR * 64 + mt * 16 + l16;
        const uint32_t ao = st + sw64(arow, kc);
        ldm_x4(afh[mt], ao);
        ldm_x4(afl[mt], ao + MATB);
      }
      uint32_t bfh[2][4], bfl[2][4];
#pragma unroll
      for (int p = 0; p < 2; p++) {
        const int brow = wC * 32 + p * 16 + l16;
        const uint32_t bo = st + 2 * MATB + sw64(brow, kc);
        ldm_x4(bfh[p], bo);
        ldm_x4(bfl[p], bo + MATB);
      }
#pragma unroll
      for (int p = 0; p < 2; p++) {
#pragma unroll
        for (int mt = 0; mt < 4; mt++) {
          mma16816(acc[mt][2 * p],     afh[mt], bfh[p][0], bfh[p][2]);
          mma16816(acc[mt][2 * p],     afh[mt], bfl[p][0], bfl[p][2]);
          mma16816(acc[mt][2 * p],     afl[mt], bfh[p][0], bfh[p][2]);
          mma16816(acc[mt][2 * p + 1], afh[mt], bfh[p][1], bfh[p][3]);
          mma16816(acc[mt][2 * p + 1], afh[mt], bfl[p][1], bfl[p][3]);
          mma16816(acc[mt][2 * p + 1], afl[mt], bfh[p][1], bfh[p][3]);
        }
      }
    }
  }

  // epilogue
  const int gid = lane >> 2, tig = lane & 3;
#pragma unroll
  for (int mt = 0; mt < 4; mt++) {
    const int row = bm + wR * 64 + mt * 16 + gid;
#pragma unroll
    for (int nt = 0; nt < 4; nt++) {
      const int col = bn + wC * 32 + nt * 8 + tig * 2;
      if (col < Nn) {
        float v[4] = {acc[mt][nt][0], acc[mt][nt][1], acc[mt][nt][2], acc[mt][nt][3]};
        if (EPI == 1) {
          const float d0 = dt_bias[col], d1 = dt_bias[col + 1];
          const float na = -expf(A_log[col >> 7]);
#pragma unroll
          for (int r = 0; r < 4; r++) {
            float x = v[r] + ((r & 1) ? d1 : d0);
            float sp = (x > 20.f) ? x : log1pf(expf(x));
            v[r] = expf(na * sp);
          }
        }
        *reinterpret_cast<float2*>(C + (size_t)row * ldc + col) = make_float2(v[0], v[1]);
        *reinterpret_cast<float2*>(C + (size_t)(row + 8) * ldc + col) = make_float2(v[2], v[3]);
      }
    }
  }
}

// ======================= fp32 -> bf16 hi/lo split (vectorized x4) =======================
__global__ void __launch_bounds__(256) split_bf16_kernel(
    const float* __restrict__ src, int srcStride, int cols,
    __nv_bfloat16* __restrict__ hi, __nv_bfloat16* __restrict__ lo, int total4) {
  int i = blockIdx.x * 256 + threadIdx.x;
  if (i >= total4) return;
  const int idx = i * 4;
  const int r = idx / cols, c = idx - r * cols;
  const float4 x = *reinterpret_cast<const float4*>(src + (size_t)r * srcStride + c);
  __nv_bfloat16 h0 = __float2bfloat16_rn(x.x), h1 = __float2bfloat16_rn(x.y);
  __nv_bfloat16 h2 = __float2bfloat16_rn(x.z), h3 = __float2bfloat16_rn(x.w);
  __nv_bfloat16 l0 = __float2bfloat16_rn(x.x - __bfloat162float(h0));
  __nv_bfloat16 l1 = __float2bfloat16_rn(x.y - __bfloat162float(h1));
  __nv_bfloat16 l2 = __float2bfloat16_rn(x.z - __bfloat162float(h2));
  __nv_bfloat16 l3 = __float2bfloat16_rn(x.w - __bfloat162float(h3));
  uint2 hw, lw;
  hw.x = (uint32_t)bf16_bits(h0) | ((uint32_t)bf16_bits(h1) << 16);
  hw.y = (uint32_t)bf16_bits(h2) | ((uint32_t)bf16_bits(h3) << 16);
  lw.x = (uint32_t)bf16_bits(l0) | ((uint32_t)bf16_bits(l1) << 16);
  lw.y = (uint32_t)bf16_bits(l2) | ((uint32_t)bf16_bits(l3) << 16);
  *reinterpret_cast<uint2*>(hi + idx) = hw;
  *reinterpret_cast<uint2*>(lo + idx) = lw;
}

// stacked small-weight matrix [Wfa;Wga;Wb;zeros] -> bf16 hi/lo [384, HID]
__global__ void __launch_bounds__(256) ws_build_kernel(
    const float* __restrict__ Wfa, const float* __restrict__ Wga,
    const float* __restrict__ Wb,
    __nv_bfloat16* __restrict__ hi, __nv_bfloat16* __restrict__ lo) {
  int idx = blockIdx.x * 256 + threadIdx.x;
  if (idx >= NS_PAD * HID) return;
  int r = idx / HID, c = idx - r * HID;
  float x = 0.f;
  if (r < 128) x = Wfa[r * HID + c];
  else if (r < 256) x = Wga[(r - 128) * HID + c];
  else if (r < NS_COMB) x = Wb[(r - 256) * HID + c];
  __nv_bfloat16 h = __float2bfloat16_rn(x);
  hi[idx] = h;
  lo[idx] = __float2bfloat16_rn(x - __bfloat162float(h));
}

// -------- fused depthwise causal conv(K=4) + SiLU for Q,K,V in one launch --------
// grid (3*NH, NSEQ); type 0=q (norm+scale), 1=k (norm), 2=v (plain)
__global__ void __launch_bounds__(128) conv_silu_fused_kernel(
    const float* __restrict__ QKV,
    const float* __restrict__ Wq, const float* __restrict__ Wk, const float* __restrict__ Wv,
    float* __restrict__ Qc, float* __restrict__ Kc, float* __restrict__ Vc) {
  const int type = blockIdx.x >> 5;         // /NH
  const int h = blockIdx.x & 31;
  const int n = blockIdx.y;
  const int tid = threadIdx.x;
  const int c = h * DK + tid;
  const float* W = (type == 0) ? Wq : (type == 1) ? Wk : Wv;
  float* Y = (type == 0) ? Qc : (type == 1) ? Kc : Vc;
  const float* X = QKV + type * PROJ;

  float y = 0.f;
#pragma unroll
  for (int i = 0; i < 4; i++) {
    int nn = n - 3 + i;
    if (nn >= 0) y = fmaf(X[(size_t)nn * QKVN + c], W[c * 4 + i], y);
  }
  y = y / (1.f + expf(-y));  // SiLU
  if (type < 2) {
    __shared__ float red[4];
    float ss = y * y;
#pragma unroll
    for (int o = 16; o > 0; o >>= 1) ss += __shfl_xor_sync(0xffffffffu, ss, o);
    if ((tid & 31) == 0) red[tid >> 5] = ss;
    __syncthreads();
    float tot = red[0] + red[1] + red[2] + red[3];
    y *= rsqrtf(tot + 1e-6f) * ((type == 0) ? QSCALE : 1.0f);
  }
  Y[(size_t)n * PROJ + c] = y;
}

// ---------------- sequential delta-rule scan ----------------
__global__ void __launch_bounds__(256, 1) scan_kernel(
    const float* __restrict__ Q, const float* __restrict__ K,
    const float* __restrict__ V, const float* __restrict__ EG,
    const float* __restrict__ BRAW, int bstride, float* __restrict__ O) {
  const int h = blockIdx.x >> 2;
  const int vbase = (blockIdx.x & 3) << 5;
  const int tid = threadIdx.x;
  const int vloc = tid >> 3;
  const int kc = tid & 7;

  __shared__ float k_sh[2][128], q_sh[2][128], e_sh[2][128];
  __shared__ float v_sh[2][32];
  __shared__ float b_sh[2];

  float S[16];
#pragma unroll
  for (int j = 0; j < 16; j++) S[j] = 0.f;

  const size_t hb = (size_t)h * DK;
  float pk = 0.f, pe = 0.f, pq = 0.f, pv = 0.f, pb = 0.f;

  if (tid < 128) {
    pk = K[hb + tid];
    pe = EG[hb + tid];
  } else {
    int u = tid - 128;
    pq = Q[hb + u];
    if (u < 32) pv = V[hb + vbase + u];
    if (u == 127) pb = BRAW[h];
  }

  for (int t = 0; t < NSEQ; t++) {
    const int buf = t & 1;
    if (tid < 128) {
      int sw = ((tid & 15) << 3) | (tid >> 4);
      k_sh[buf][sw] = pk;
      e_sh[buf][sw] = pe;
    } else {
      int u = tid - 128;
      q_sh[buf][((u & 15) << 3) | (u >> 4)] = pq;
      if (u < 32) v_sh[buf][u] = pv;
      if (u == 127) b_sh[buf] = 1.f / (1.f + expf(-pb));
    }
    __syncthreads();

    if (t + 1 < NSEQ) {
      size_t off = (size_t)(t + 1) * PROJ + hb;
      if (tid < 128) {
        pk = K[off + tid];
        pe = EG[off + tid];
      } else {
        int u = tid - 128;
        pq = Q[off + u];
        if (u < 32) pv = V[off + vbase + u];
        if (u == 127) pb = BRAW[(size_t)(t + 1) * bstride + h];
      }
    }

    float kreg[16];
    float kv0 = 0.f, kv1 = 0.f;
#pragma unroll
    for (int j = 0; j < 16; j++) {
      float e = e_sh[buf][(j << 3) | kc];
      float kk = k_sh[buf][(j << 3) | kc];
      kreg[j] = kk;
      float s = S[j] * e;
      S[j] = s;
      if (j & 1) kv1 = fmaf(kk, s, kv1); else kv0 = fmaf(kk, s, kv0);
    }
    float kv = kv0 + kv1;
    kv += __shfl_xor_sync(0xffffffffu, kv, 1);
    kv += __shfl_xor_sync(0xffffffffu, kv, 2);
    kv += __shfl_xor_sync(0xffffffffu, kv, 4);

    const float delta = (v_sh[buf][vloc] - kv) * b_sh[buf];

    float o0 = 0.f, o1 = 0.f;
#pragma unroll
    for (int j = 0; j < 16; j++) {
      float q = q_sh[buf][(j << 3) | kc];
      float s = fmaf(kreg[j], delta, S[j]);
      S[j] = s;
      if (j & 1) o1 = fmaf(q, s, o1); else o0 = fmaf(q, s, o0);
    }
    float o = o0 + o1;
    o += __shfl_xor_sync(0xffffffffu, o, 1);
    o += __shfl_xor_sync(0xffffffffu, o, 2);
    o += __shfl_xor_sync(0xffffffffu, o, 4);
    if (kc == 0) O[(size_t)t * PROJ + hb + vbase + vloc] = o;
    __syncthreads();
  }
}

// -------- gated RMSNorm -> bf16 hi/lo directly (paired 4B stores) --------
__global__ void __launch_bounds__(128) out_gate_kernel(
    const float* __restrict__ CORE, const float* __restrict__ GATE,
    const float* __restrict__ onorm_w,
    __nv_bfloat16* __restrict__ hi, __nv_bfloat16* __restrict__ lo) {
  const int h = blockIdx.x;
  const int n = blockIdx.y;
  const int tid = threadIdx.x;
  const size_t idx = (size_t)n * PROJ + h * DK + tid;
  float cv = CORE[idx];
  float ss = cv * cv;
#pragma unroll
  for (int o = 16; o > 0; o >>= 1) ss += __shfl_xor_sync(0xffffffffu, ss, o);
  __shared__ float red[4];
  if ((tid & 31) == 0) red[tid >> 5] = ss;
  __syncthreads();
  float tot = red[0] + red[1] + red[2] + red[3];
  float r = rsqrtf(tot * (1.f / 128.f) + 1e-5f);
  float gt = GATE[idx];
  float v = cv * r * onorm_w[tid] / (1.f + expf(-gt));
  __nv_bfloat16 hh = __float2bfloat16_rn(v);
  __nv_bfloat16 ll = __float2bfloat16_rn(v - __bfloat162float(hh));
  uint32_t hw = bf16_bits(hh), lw = bf16_bits(ll);
  uint32_t hn = __shfl_down_sync(0xffffffffu, hw, 1);
  uint32_t ln = __shfl_down_sync(0xffffffffu, lw, 1);
  if ((tid & 1) == 0) {
    *reinterpret_cast<uint32_t*>(hi + idx) = hw | (hn << 16);
    *reinterpret_cast<uint32_t*>(lo + idx) = lw | (ln << 16);
  }
}

// ---------------- launch ----------------
extern "C" void kernel_launch(void* const* d_in, const int* in_sizes, int n_in,
                              void* d_out, int out_size) {
  const float* hs      = (const float*)d_in[0];
  const float* Wq      = (const float*)d_in[1];
  const float* Wk      = (const float*)d_in[2];
  const float* Wv      = (const float*)d_in[3];
  const float* conv_q  = (const float*)d_in[4];
  const float* conv_k  = (const float*)d_in[5];
  const float* conv_v  = (const float*)d_in[6];
  const float* Wfa     = (const float*)d_in[7];
  const float* Wfb     = (const float*)d_in[8];
  const float* dt_bias = (const float*)d_in[9];
  const float* Wb      = (const float*)d_in[10];
  const float* A_log   = (const float*)d_in[11];
  const float* Wga     = (const float*)d_in[12];
  const float* Wgb     = (const float*)d_in[13];
  const float* onorm_w = (const float*)d_in[14];
  const float* Wo      = (const float*)d_in[15];
  float* out = (float*)d_out;

  float *QKVp, *Qc, *Kc, *Vc, *F, *GATE, *CORE, *COMB;
  __nv_bfloat16 *hsh, *hsl, *Wqkvh, *Wqkvl, *Woh, *Wol;
  __nv_bfloat16 *Wfbh, *Wfbl, *Wgbh, *Wgbl, *WSh, *WSl;
  __nv_bfloat16 *FAh, *FAl, *GAh, *GAl, *COREh, *COREl;
  cudaGetSymbolAddress((void**)&QKVp,  g_QKVp);
  cudaGetSymbolAddress((void**)&Qc,    g_Qc);
  cudaGetSymbolAddress((void**)&Kc,    g_Kc);
  cudaGetSymbolAddress((void**)&Vc,    g_Vc);
  cudaGetSymbolAddress((void**)&F,     g_F);
  cudaGetSymbolAddress((void**)&GATE,  g_GATE);
  cudaGetSymbolAddress((void**)&CORE,  g_CORE);
  cudaGetSymbolAddress((void**)&COMB,  g_COMB);
  cudaGetSymbolAddress((void**)&hsh,   g_hsh);
  cudaGetSymbolAddress((void**)&hsl,   g_hsl);
  cudaGetSymbolAddress((void**)&Wqkvh, g_Wqkvh);
  cudaGetSymbolAddress((void**)&Wqkvl, g_Wqkvl);
  cudaGetSymbolAddress((void**)&Woh,   g_Woh);
  cudaGetSymbolAddress((void**)&Wol,   g_Wol);
  cudaGetSymbolAddress((void**)&Wfbh,  g_Wfbh);
  cudaGetSymbolAddress((void**)&Wfbl,  g_Wfbl);
  cudaGetSymbolAddress((void**)&Wgbh,  g_Wgbh);
  cudaGetSymbolAddress((void**)&Wgbl,  g_Wgbl);
  cudaGetSymbolAddress((void**)&WSh,   g_WSh);
  cudaGetSymbolAddress((void**)&WSl,   g_WSl);
  cudaGetSymbolAddress((void**)&FAh,   g_FAh);
  cudaGetSymbolAddress((void**)&FAl,   g_FAl);
  cudaGetSymbolAddress((void**)&GAh,   g_GAh);
  cudaGetSymbolAddress((void**)&GAl,   g_GAl);
  cudaGetSymbolAddress((void**)&COREh, g_COREh);
  cudaGetSymbolAddress((void**)&COREl, g_COREl);

  cudaFuncSetAttribute(gemm_bf16s<0>, cudaFuncAttributeMaxDynamicSharedMemorySize, SMEMB);
  cudaFuncSetAttribute(gemm_bf16s<1>, cudaFuncAttributeMaxDynamicSharedMemorySize, SMEMB);

  // ---- split conversions (vectorized x4) ----
  int T4;
  T4 = NSEQ * HID / 4;
  split_bf16_kernel<<<(T4 + 255) / 256, 256>>>(hs, HID, HID, hsh, hsl, T4);
  T4 = PROJ * HID / 4;
  split_bf16_kernel<<<(T4 + 255) / 256, 256>>>(Wq, HID, HID, Wqkvh, Wqkvl, T4);
  split_bf16_kernel<<<(T4 + 255) / 256, 256>>>(Wk, HID, HID, Wqkvh + (size_t)PROJ * HID,
                                               Wqkvl + (size_t)PROJ * HID, T4);
  split_bf16_kernel<<<(T4 + 255) / 256, 256>>>(Wv, HID, HID, Wqkvh + (size_t)2 * PROJ * HID,
                                               Wqkvl + (size_t)2 * PROJ * HID, T4);
  T4 = HID * PROJ / 4;
  split_bf16_kernel<<<(T4 + 255) / 256, 256>>>(Wo, PROJ, PROJ, Woh, Wol, T4);
  T4 = PROJ * DK / 4;
  split_bf16_kernel<<<(T4 + 255) / 256, 256>>>(Wfb, DK, DK, Wfbh, Wfbl, T4);
  split_bf16_kernel<<<(T4 + 255) / 256, 256>>>(Wgb, DK, DK, Wgbh, Wgbl, T4);
  ws_build_kernel<<<(NS_PAD * HID + 255) / 256, 256>>>(Wfa, Wga, Wb, WSh, WSl);

  // ---- tensor-core GEMMs: fused QKV + fused small (FA|GA|beta) ----
  gemm_bf16s<0><<<dim3(QKVN / 128, NSEQ / 128), 256, SMEMB>>>(
      hsh, hsl, Wqkvh, Wqkvl, QKVp, QKVN, HID, QKVN, nullptr, nullptr);
  gemm_bf16s<0><<<dim3(3, NSEQ / 128), 256, SMEMB>>>(
      hsh, hsl, WSh, WSl, COMB, NS_COMB, HID, NS_COMB, nullptr, nullptr);

  // ---- fused conv + silu (+ l2 norm for q,k) ----
  conv_silu_fused_kernel<<<dim3(3 * NH, NSEQ), 128>>>(QKVp, conv_q, conv_k, conv_v, Qc, Kc, Vc);

  // ---- low-rank second projections (K=128), F with fused decay epilogue ----
  T4 = NSEQ * DK / 4;
  split_bf16_kernel<<<(T4 + 255) / 256, 256>>>(COMB, NS_COMB, DK, FAh, FAl, T4);
  split_bf16_kernel<<<(T4 + 255) / 256, 256>>>(COMB + DK, NS_COMB, DK, GAh, GAl, T4);
  gemm_bf16s<1><<<dim3(PROJ / 128, NSEQ / 128), 256, SMEMB>>>(
      FAh, FAl, Wfbh, Wfbl, F, PROJ, DK, PROJ, dt_bias, A_log);
  gemm_bf16s<0><<<dim3(PROJ / 128, NSEQ / 128), 256, SMEMB>>>(
      GAh, GAl, Wgbh, Wgbl, GATE, PROJ, DK, PROJ, nullptr, nullptr);

  // ---- recurrent scan ----
  scan_kernel<<<NH * 4, 256>>>(Qc, Kc, Vc, F, COMB + 256, NS_COMB, CORE);

  // ---- gated rmsnorm -> bf16 hi/lo directly ----
  dim3 gConv(NH, NSEQ);
  out_gate_kernel<<<gConv, 128>>>(CORE, GATE, onorm_w, COREh, COREl);

  // ---- output projection ----
  gemm_bf16s<0><<<dim3(HID / 128, NSEQ / 128), 256, SMEMB>>>(
      COREh, COREl, Woh, Wol, out, HID, PROJ, HID, nullptr, nullptr);
}

// round 9
// speedup vs baseline: 2.4400x; 1.1764x over previous
#include <cuda_runtime.h>
#include <cuda_fp16.h>
#include <math.h>
#include <stdint.h>

#define NSEQ 2048
#define HID  2048
#define NH   32
#define DK   128
#define PROJ 4096
#define QKVN (3 * PROJ)
#define QSCALE 0.08838834764831843f     // 128^-0.5

#define NS_COMB   288                    // Wfa(128) + Wga(128) + Wb(32)
#define NS_PAD    384

// ---- GEMM tiling ----
#define BM 128
#define BN 128
#define BK 32
#define MATB   (128 * 64)                // one matrix tile: 128 rows x 64B = 8KB
#define STAGEB (3 * MATB)                // Ah,Al,Bh = 24KB
#define NSTG   4
#define SMEMB  (NSTG * STAGEB)           // 96KB -> 2 CTAs/SM

// ---------------- scratch (device globals; no allocation allowed) ----------------
__device__ __align__(256) float g_QKVp[NSEQ * QKVN];
__device__ __align__(256) float g_Qc[NSEQ * PROJ];
__device__ __align__(256) float g_Kc[NSEQ * PROJ];
__device__ __align__(256) float g_Vc[NSEQ * PROJ];
__device__ __align__(256) float g_F[NSEQ * PROJ];      // exp(g) written by GEMM epilogue
__device__ __align__(256) float g_GATE[NSEQ * PROJ];
__device__ __align__(256) float g_CORE[NSEQ * PROJ];
__device__ __align__(256) float g_COMB[NSEQ * NS_COMB];

__device__ __align__(256) __half g_hsh[NSEQ * HID];
__device__ __align__(256) __half g_hsl[NSEQ * HID];
__device__ __align__(256) __half g_Wqkvh[QKVN * HID];
__device__ __align__(256) __half g_Woh[HID * PROJ];
__device__ __align__(256) __half g_Wfbh[PROJ * DK];
__device__ __align__(256) __half g_Wgbh[PROJ * DK];
__device__ __align__(256) __half g_WSh[NS_PAD * HID];
__device__ __align__(256) __half g_FAh[NSEQ * DK];
__device__ __align__(256) __half g_FAl[NSEQ * DK];
__device__ __align__(256) __half g_GAh[NSEQ * DK];
__device__ __align__(256) __half g_GAl[NSEQ * DK];
__device__ __align__(256) __half g_COREh[NSEQ * PROJ];
__device__ __align__(256) __half g_COREl[NSEQ * PROJ];

// ============================ helpers (sm_80-portable PTX only) ============================
__device__ __forceinline__ uint32_t smem_u32(const void* p) {
  return (uint32_t)__cvta_generic_to_shared(p);
}
__device__ __forceinline__ void cp_async16(uint32_t dst, const void* src) {
  asm volatile("cp.async.cg.shared.global [%0], [%1], 16;" :: "r"(dst), "l"(src) : "memory");
}
__device__ __forceinline__ void cp_commit() {
  asm volatile("cp.async.commit_group;" ::: "memory");
}
template<int N> __device__ __forceinline__ void cp_wait() {
  asm volatile("cp.async.wait_group %0;" :: "n"(N) : "memory");
}
__device__ __forceinline__ void ldm_x4(uint32_t* r, uint32_t addr) {
  asm volatile("ldmatrix.sync.aligned.m8n8.x4.shared.b16 {%0,%1,%2,%3}, [%4];"
               : "=r"(r[0]), "=r"(r[1]), "=r"(r[2]), "=r"(r[3]) : "r"(addr));
}
__device__ __forceinline__ void mma16816(float* c, const uint32_t* a,
                                         uint32_t b0, uint32_t b1) {
  asm volatile(
      "mma.sync.aligned.m16n8k16.row.col.f32.f16.f16.f32 "
      "{%0,%1,%2,%3}, {%4,%5,%6,%7}, {%8,%9}, {%0,%1,%2,%3};"
      : "+f"(c[0]), "+f"(c[1]), "+f"(c[2]), "+f"(c[3])
      : "r"(a[0]), "r"(a[1]), "r"(a[2]), "r"(a[3]), "r"(b0), "r"(b1));
}
__device__ __forceinline__ uint16_t h_bits(__half h) {
  return *reinterpret_cast<uint16_t*>(&h);
}
// 64B-row swizzle: chunk' = kc ^ ((row>>1)&3); conflict-free for cp.async stores
// and ldmatrix 8-row phases.
__device__ __forceinline__ uint32_t sw64(int row, int kc) {
  return (uint32_t)(row * 64 + ((kc ^ ((row >> 1) & 3)) << 4));
}

// ======================= fp16 hi/lo 2-pass GEMM (mma.sync + ldmatrix) =======================
// C[M,Nn] = A[M,K] * B[Nn,K]^T ; 2 passes: Ah*Bh + Al*Bh (A split, B hi-only).
// EPI: 0 = plain fp32 store, 1 = decay-gate epilogue.
__device__ __forceinline__ void ld_stage(uint32_t sb, int slot, int kt, int tid,
                                         const char* a_h, const char* a_l,
                                         const char* b_h, size_t kbytes) {
  const uint32_t st = sb + (uint32_t)slot * STAGEB;
#pragma unroll
  for (int i = 0; i < 2; i++) {
    const int chunk = i * 256 + tid;          // 0..511 (128 rows x 4 chunks)
    const int row = chunk >> 2, kc = chunk & 3;
    const uint32_t so = sw64(row, kc);
    const size_t go = (size_t)row * kbytes + (size_t)kt * 64 + (size_t)(kc << 4);
    cp_async16(st + so,            a_h + go);
    cp_async16(st + MATB + so,     a_l + go);
    cp_async16(st + 2 * MATB + so, b_h + go);
  }
  cp_commit();
}

template <int EPI>
__global__ void __launch_bounds__(256, 2) gemm_f16s(
    const __half* __restrict__ Ah, const __half* __restrict__ Al,
    const __half* __restrict__ Bh,
    float* __restrict__ C, int Nn, int K, int ldc,
    const float* __restrict__ dt_bias, const float* __restrict__ A_log) {
  extern __shared__ char sm[];
  const int tid = threadIdx.x;
  const int bm = blockIdx.y * BM, bn = blockIdx.x * BN;
  const uint32_t sb = smem_u32(sm);

  const int lane = tid & 31, warp = tid >> 5;
  const int l16 = lane & 15, lh = lane >> 4;
  const int wR = warp >> 2;            // 0..1  (M, 64 rows)
  const int wC = warp & 3;             // 0..3  (N, 32 cols)

  const size_t kbytes = (size_t)K * 2;
  const char* a_h = (const char*)Ah + (size_t)bm * kbytes;
  const char* a_l = (const char*)Al + (size_t)bm * kbytes;
  const char* b_h = (const char*)Bh + (size_t)bn * kbytes;

  float acc[4][4][4];
#pragma unroll
  for (int i = 0; i < 4; i++)
#pragma unroll
    for (int j = 0; j < 4; j++)
#pragma unroll
      for (int r = 0; r < 4; r++) acc[i][j][r] = 0.f;

  const int KT = K / BK;
  for (int s = 0; s < NSTG - 1 && s < KT; s++)
    ld_stage(sb, s, s, tid, a_h, a_l, b_h, kbytes);

#pragma unroll 1
  for (int kt = 0; kt < KT; kt++) {
    const int slot = kt % NSTG;
    int pend = KT - 1 - kt; if (pend > NSTG - 2) pend = NSTG - 2;
    if (pend >= 2) cp_wait<2>(); else if (pend == 1) cp_wait<1>(); else cp_wait<0>();
    __syncthreads();

    const int nk = kt + NSTG - 1;
    if (nk < KT) ld_stage(sb, nk % NSTG, nk, tid, a_h, a_l, b_h, kbytes);

    const uint32_t st = sb + (uint32_t)slot * STAGEB;
#pragma unroll
    for (int kk = 0; kk < 2; kk++) {
      const int kc = kk * 2 + lh;       // 16B chunk index within 64B row
      uint32_t afh[4][4], afl[4][4];
#pragma unroll
      for (int mt = 0; mt < 4; mt++) {
        const int arow = wR * 64 + mt * 16 + l16;
        const uint32_t ao = st + sw64(arow, kc);
        ldm_x4(afh[mt], ao);
        ldm_x4(afl[mt], ao + MATB);
      }
      uint32_t bfh[2][4];
#pragma unroll
      for (int p = 0; p < 2; p++) {
        const int brow = wC * 32 + p * 16 + l16;
        ldm_x4(bfh[p], st + 2 * MATB + sw64(brow, kc));
      }
#pragma unroll
      for (int p = 0; p < 2; p++) {
#pragma unroll
        for (int mt = 0; mt < 4; mt++) {
          mma16816(acc[mt][2 * p],     afh[mt], bfh[p][0], bfh[p][2]);
          mma16816(acc[mt][2 * p],     afl[mt], bfh[p][0], bfh[p][2]);
          mma16816(acc[mt][2 * p + 1], afh[mt], bfh[p][1], bfh[p][3]);
          mma16816(acc[mt][2 * p + 1], afl[mt], bfh[p][1], bfh[p][3]);
        }
      }
    }
  }

  // epilogue
  const int gid = lane >> 2, tig = lane & 3;
#pragma unroll
  for (int mt = 0; mt < 4; mt++) {
    const int row = bm + wR * 64 + mt * 16 + gid;
#pragma unroll
    for (int nt = 0; nt < 4; nt++) {
      const int col = bn + wC * 32 + nt * 8 + tig * 2;
      if (col < Nn) {
        float v[4] = {acc[mt][nt][0], acc[mt][nt][1], acc[mt][nt][2], acc[mt][nt][3]};
        if (EPI == 1) {
          const float d0 = dt_bias[col], d1 = dt_bias[col + 1];
          const float na = -expf(A_log[col >> 7]);
#pragma unroll
          for (int r = 0; r < 4; r++) {
            float x = v[r] + ((r & 1) ? d1 : d0);
            float sp = (x > 20.f) ? x : log1pf(expf(x));
            v[r] = expf(na * sp);
          }
        }
        *reinterpret_cast<float2*>(C + (size_t)row * ldc + col) = make_float2(v[0], v[1]);
        *reinterpret_cast<float2*>(C + (size_t)(row + 8) * ldc + col) = make_float2(v[2], v[3]);
      }
    }
  }
}

// ======================= fp32 -> fp16 hi/lo split (vectorized x4; lo optional) =======================
__global__ void __launch_bounds__(256) split_f16_kernel(
    const float* __restrict__ src, int srcStride, int cols,
    __half* __restrict__ hi, __half* __restrict__ lo, int total4) {
  int i = blockIdx.x * 256 + threadIdx.x;
  if (i >= total4) return;
  const int idx = i * 4;
  const int r = idx / cols, c = idx - r * cols;
  const float4 x = *reinterpret_cast<const float4*>(src + (size_t)r * srcStride + c);
  __half h0 = __float2half_rn(x.x), h1 = __float2half_rn(x.y);
  __half h2 = __float2half_rn(x.z), h3 = __float2half_rn(x.w);
  uint2 hw;
  hw.x = (uint32_t)h_bits(h0) | ((uint32_t)h_bits(h1) << 16);
  hw.y = (uint32_t)h_bits(h2) | ((uint32_t)h_bits(h3) << 16);
  *reinterpret_cast<uint2*>(hi + idx) = hw;
  if (lo) {
    __half l0 = __float2half_rn(x.x - __half2float(h0));
    __half l1 = __float2half_rn(x.y - __half2float(h1));
    __half l2 = __float2half_rn(x.z - __half2float(h2));
    __half l3 = __float2half_rn(x.w - __half2float(h3));
    uint2 lw;
    lw.x = (uint32_t)h_bits(l0) | ((uint32_t)h_bits(l1) << 16);
    lw.y = (uint32_t)h_bits(l2) | ((uint32_t)h_bits(l3) << 16);
    *reinterpret_cast<uint2*>(lo + idx) = lw;
  }
}

// stacked small-weight matrix [Wfa;Wga;Wb;zeros] -> fp16 hi [384, HID]
__global__ void __launch_bounds__(256) ws_build_kernel(
    const float* __restrict__ Wfa, const float* __restrict__ Wga,
    const float* __restrict__ Wb, __half* __restrict__ hi) {
  int idx = blockIdx.x * 256 + threadIdx.x;
  if (idx >= NS_PAD * HID) return;
  int r = idx / HID, c = idx - r * HID;
  float x = 0.f;
  if (r < 128) x = Wfa[r * HID + c];
  else if (r < 256) x = Wga[(r - 128) * HID + c];
  else if (r < NS_COMB) x = Wb[(r - 256) * HID + c];
  hi[idx] = __float2half_rn(x);
}

// -------- fused depthwise causal conv(K=4) + SiLU for Q,K,V in one launch --------
__global__ void __launch_bounds__(128) conv_silu_fused_kernel(
    const float* __restrict__ QKV,
    const float* __restrict__ Wq, const float* __restrict__ Wk, const float* __restrict__ Wv,
    float* __restrict__ Qc, float* __restrict__ Kc, float* __restrict__ Vc) {
  const int type = blockIdx.x >> 5;         // /NH
  const int h = blockIdx.x & 31;
  const int n = blockIdx.y;
  const int tid = threadIdx.x;
  const int c = h * DK + tid;
  const float* W = (type == 0) ? Wq : (type == 1) ? Wk : Wv;
  float* Y = (type == 0) ? Qc : (type == 1) ? Kc : Vc;
  const float* X = QKV + type * PROJ;

  float y = 0.f;
#pragma unroll
  for (int i = 0; i < 4; i++) {
    int nn = n - 3 + i;
    if (nn >= 0) y = fmaf(X[(size_t)nn * QKVN + c], W[c * 4 + i], y);
  }
  y = y / (1.f + expf(-y));  // SiLU
  if (type < 2) {
    __shared__ float red[4];
    float ss = y * y;
#pragma unroll
    for (int o = 16; o > 0; o >>= 1) ss += __shfl_xor_sync(0xffffffffu, ss, o);
    if ((tid & 31) == 0) red[tid >> 5] = ss;
    __syncthreads();
    float tot = red[0] + red[1] + red[2] + red[3];
    y *= rsqrtf(tot + 1e-6f) * ((type == 0) ? QSCALE : 1.0f);
  }
  Y[(size_t)n * PROJ + c] = y;
}

// ---------------- sequential delta-rule scan (single reduce phase) ----------------
// o_t = q.S_decayed + (q.k) * delta ; S_new = S_decayed + k (x) delta
__global__ void __launch_bounds__(256, 1) scan_kernel(
    const float* __restrict__ Q, const float* __restrict__ K,
    const float* __restrict__ V, const float* __restrict__ EG,
    const float* __restrict__ BRAW, int bstride, float* __restrict__ O) {
  const int h = blockIdx.x >> 2;
  const int vbase = (blockIdx.x & 3) << 5;
  const int tid = threadIdx.x;
  const int vloc = tid >> 3;
  const int kc = tid & 7;

  __shared__ float k_sh[2][128], q_sh[2][128], e_sh[2][128];
  __shared__ float v_sh[2][32];
  __shared__ float b_sh[2];

  float S[16];
#pragma unroll
  for (int j = 0; j < 16; j++) S[j] = 0.f;

  const size_t hb = (size_t)h * DK;
  float pk = 0.f, pe = 0.f, pq = 0.f, pv = 0.f, pb = 0.f;

  if (tid < 128) {
    pk = K[hb + tid];
    pe = EG[hb + tid];
  } else {
    int u = tid - 128;
    pq = Q[hb + u];
    if (u < 32) pv = V[hb + vbase + u];
    if (u == 127) pb = BRAW[h];
  }

  for (int t = 0; t < NSEQ; t++) {
    const int buf = t & 1;
    if (tid < 128) {
      int sw = ((tid & 15) << 3) | (tid >> 4);
      k_sh[buf][sw] = pk;
      e_sh[buf][sw] = pe;
    } else {
      int u = tid - 128;
      q_sh[buf][((u & 15) << 3) | (u >> 4)] = pq;
      if (u < 32) v_sh[buf][u] = pv;
      if (u == 127) b_sh[buf] = 1.f / (1.f + expf(-pb));
    }
    __syncthreads();

    if (t + 1 < NSEQ) {
      size_t off = (size_t)(t + 1) * PROJ + hb;
      if (tid < 128) {
        pk = K[off + tid];
        pe = EG[off + tid];
      } else {
        int u = tid - 128;
        pq = Q[off + u];
        if (u < 32) pv = V[off + vbase + u];
        if (u == 127) pb = BRAW[(size_t)(t + 1) * bstride + h];
      }
    }

    float kreg[16];
    float kv0 = 0.f, kv1 = 0.f, qs0 = 0.f, qs1 = 0.f, qk0 = 0.f, qk1 = 0.f;
#pragma unroll
    for (int j = 0; j < 16; j++) {
      const float e  = e_sh[buf][(j << 3) | kc];
      const float kk = k_sh[buf][(j << 3) | kc];
      const float qq = q_sh[buf][(j << 3) | kc];
      const float s = S[j] * e;
      S[j] = s;
      kreg[j] = kk;
      if (j & 1) {
        kv1 = fmaf(kk, s, kv1); qs1 = fmaf(qq, s, qs1); qk1 = fmaf(qq, kk, qk1);
      } else {
        kv0 = fmaf(kk, s, kv0); qs0 = fmaf(qq, s, qs0); qk0 = fmaf(qq, kk, qk0);
      }
    }
    float kv = kv0 + kv1, qs = qs0 + qs1, qk = qk0 + qk1;
#pragma unroll
    for (int o = 1; o < 8; o <<= 1) {
      kv += __shfl_xor_sync(0xffffffffu, kv, o);
      qs += __shfl_xor_sync(0xffffffffu, qs, o);
      qk += __shfl_xor_sync(0xffffffffu, qk, o);
    }

    const float delta = (v_sh[buf][vloc] - kv) * b_sh[buf];
    if (kc == 0) O[(size_t)t * PROJ + hb + vbase + vloc] = fmaf(qk, delta, qs);

#pragma unroll
    for (int j = 0; j < 16; j++) S[j] = fmaf(kreg[j], delta, S[j]);
    __syncthreads();
  }
}

// -------- gated RMSNorm -> fp16 hi/lo directly (paired 4B stores) --------
__global__ void __launch_bounds__(128) out_gate_kernel(
    const float* __restrict__ CORE, const float* __restrict__ GATE,
    const float* __restrict__ onorm_w,
    __half* __restrict__ hi, __half* __restrict__ lo) {
  const int h = blockIdx.x;
  const int n = blockIdx.y;
  const int tid = threadIdx.x;
  const size_t idx = (size_t)n * PROJ + h * DK + tid;
  float cv = CORE[idx];
  float ss = cv * cv;
#pragma unroll
  for (int o = 16; o > 0; o >>= 1) ss += __shfl_xor_sync(0xffffffffu, ss, o);
  __shared__ float red[4];
  if ((tid & 31) == 0) red[tid >> 5] = ss;
  __syncthreads();
  float tot = red[0] + red[1] + red[2] + red[3];
  float r = rsqrtf(tot * (1.f / 128.f) + 1e-5f);
  float gt = GATE[idx];
  float v = cv * r * onorm_w[tid] / (1.f + expf(-gt));
  __half hh = __float2half_rn(v);
  __half ll = __float2half_rn(v - __half2float(hh));
  uint32_t hw = h_bits(hh), lw = h_bits(ll);
  uint32_t hn = __shfl_down_sync(0xffffffffu, hw, 1);
  uint32_t ln = __shfl_down_sync(0xffffffffu, lw, 1);
  if ((tid & 1) == 0) {
    *reinterpret_cast<uint32_t*>(hi + idx) = hw | (hn << 16);
    *reinterpret_cast<uint32_t*>(lo + idx) = lw | (ln << 16);
  }
}

// ---------------- launch ----------------
extern "C" void kernel_launch(void* const* d_in, const int* in_sizes, int n_in,
                              void* d_out, int out_size) {
  const float* hs      = (const float*)d_in[0];
  const float* Wq      = (const float*)d_in[1];
  const float* Wk      = (const float*)d_in[2];
  const float* Wv      = (const float*)d_in[3];
  const float* conv_q  = (const float*)d_in[4];
  const float* conv_k  = (const float*)d_in[5];
  const float* conv_v  = (const float*)d_in[6];
  const float* Wfa     = (const float*)d_in[7];
  const float* Wfb     = (const float*)d_in[8];
  const float* dt_bias = (const float*)d_in[9];
  const float* Wb      = (const float*)d_in[10];
  const float* A_log   = (const float*)d_in[11];
  const float* Wga     = (const float*)d_in[12];
  const float* Wgb     = (const float*)d_in[13];
  const float* onorm_w = (const float*)d_in[14];
  const float* Wo      = (const float*)d_in[15];
  float* out = (float*)d_out;

  float *QKVp, *Qc, *Kc, *Vc, *F, *GATE, *CORE, *COMB;
  __half *hsh, *hsl, *Wqkvh, *Woh, *Wfbh, *Wgbh, *WSh;
  __half *FAh, *FAl, *GAh, *GAl, *COREh, *COREl;
  cudaGetSymbolAddress((void**)&QKVp,  g_QKVp);
  cudaGetSymbolAddress((void**)&Qc,    g_Qc);
  cudaGetSymbolAddress((void**)&Kc,    g_Kc);
  cudaGetSymbolAddress((void**)&Vc,    g_Vc);
  cudaGetSymbolAddress((void**)&F,     g_F);
  cudaGetSymbolAddress((void**)&GATE,  g_GATE);
  cudaGetSymbolAddress((void**)&CORE,  g_CORE);
  cudaGetSymbolAddress((void**)&COMB,  g_COMB);
  cudaGetSymbolAddress((void**)&hsh,   g_hsh);
  cudaGetSymbolAddress((void**)&hsl,   g_hsl);
  cudaGetSymbolAddress((void**)&Wqkvh, g_Wqkvh);
  cudaGetSymbolAddress((void**)&Woh,   g_Woh);
  cudaGetSymbolAddress((void**)&Wfbh,  g_Wfbh);
  cudaGetSymbolAddress((void**)&Wgbh,  g_Wgbh);
  cudaGetSymbolAddress((void**)&WSh,   g_WSh);
  cudaGetSymbolAddress((void**)&FAh,   g_FAh);
  cudaGetSymbolAddress((void**)&FAl,   g_FAl);
  cudaGetSymbolAddress((void**)&GAh,   g_GAh);
  cudaGetSymbolAddress((void**)&GAl,   g_GAl);
  cudaGetSymbolAddress((void**)&COREh, g_COREh);
  cudaGetSymbolAddress((void**)&COREl, g_COREl);

  cudaFuncSetAttribute(gemm_f16s<0>, cudaFuncAttributeMaxDynamicSharedMemorySize, SMEMB);
  cudaFuncSetAttribute(gemm_f16s<1>, cudaFuncAttributeMaxDynamicSharedMemorySize, SMEMB);

  // ---- split conversions (vectorized x4) ----
  int T4;
  T4 = NSEQ * HID / 4;
  split_f16_kernel<<<(T4 + 255) / 256, 256>>>(hs, HID, HID, hsh, hsl, T4);
  T4 = PROJ * HID / 4;
  split_f16_kernel<<<(T4 + 255) / 256, 256>>>(Wq, HID, HID, Wqkvh, nullptr, T4);
  split_f16_kernel<<<(T4 + 255) / 256, 256>>>(Wk, HID, HID, Wqkvh + (size_t)PROJ * HID, nullptr, T4);
  split_f16_kernel<<<(T4 + 255) / 256, 256>>>(Wv, HID, HID, Wqkvh + (size_t)2 * PROJ * HID, nullptr, T4);
  T4 = HID * PROJ / 4;
  split_f16_kernel<<<(T4 + 255) / 256, 256>>>(Wo, PROJ, PROJ, Woh, nullptr, T4);
  T4 = PROJ * DK / 4;
  split_f16_kernel<<<(T4 + 255) / 256, 256>>>(Wfb, DK, DK, Wfbh, nullptr, T4);
  split_f16_kernel<<<(T4 + 255) / 256, 256>>>(Wgb, DK, DK, Wgbh, nullptr, T4);
  ws_build_kernel<<<(NS_PAD * HID + 255) / 256, 256>>>(Wfa, Wga, Wb, WSh);

  // ---- tensor-core GEMMs: fused QKV + fused small (FA|GA|beta) ----
  gemm_f16s<0><<<dim3(QKVN / 128, NSEQ / 128), 256, SMEMB>>>(
      hsh, hsl, Wqkvh, QKVp, QKVN, HID, QKVN, nullptr, nullptr);
  gemm_f16s<0><<<dim3(3, NSEQ / 128), 256, SMEMB>>>(
      hsh, hsl, WSh, COMB, NS_COMB, HID, NS_COMB, nullptr, nullptr);

  // ---- fused conv + silu (+ l2 norm for q,k) ----
  conv_silu_fused_kernel<<<dim3(3 * NH, NSEQ), 128>>>(QKVp, conv_q, conv_k, conv_v, Qc, Kc, Vc);

  // ---- low-rank second projections (K=128), F with fused decay epilogue ----
  T4 = NSEQ * DK / 4;
  split_f16_kernel<<<(T4 + 255) / 256, 256>>>(COMB, NS_COMB, DK, FAh, FAl, T4);
  split_f16_kernel<<<(T4 + 255) / 256, 256>>>(COMB + DK, NS_COMB, DK, GAh, GAl, T4);
  gemm_f16s<1><<<dim3(PROJ / 128, NSEQ / 128), 256, SMEMB>>>(
      FAh, FAl, Wfbh, F, PROJ, DK, PROJ, dt_bias, A_log);
  gemm_f16s<0><<<dim3(PROJ / 128, NSEQ / 128), 256, SMEMB>>>(
      GAh, GAl, Wgbh, GATE, PROJ, DK, PROJ, nullptr, nullptr);

  // ---- recurrent scan ----
  scan_kernel<<<NH * 4, 256>>>(Qc, Kc, Vc, F, COMB + 256, NS_COMB, CORE);

  // ---- gated rmsnorm -> fp16 hi/lo directly ----
  dim3 gConv(NH, NSEQ);
  out_gate_kernel<<<gConv, 128>>>(CORE, GATE, onorm_w, COREh, COREl);

  // ---- output projection ----
  gemm_f16s<0><<<dim3(HID / 128, NSEQ / 128), 256, SMEMB>>>(
      COREh, COREl, Woh, out, HID, PROJ, HID, nullptr, nullptr);
}